// round 1
// baseline (speedup 1.0000x reference)
#include <cuda_runtime.h>
#include <math.h>

#define NN   50000
#define NE   300000
#define NDIM 11
#define EDIM 5
#define HID  256
#define NG   1024
#define NL   4
#define BN_EPS 1e-5f

// ---------------- scratch (device globals: allocation-free) ----------------
__device__ float g_h [NN*HID];
__device__ float g_z0[NN*HID];
__device__ float g_z1[NN*HID];
__device__ float g_z2[NN*HID];
__device__ int   g_deg[NN];
__device__ int   g_offs[NN+1];
__device__ int   g_cursor[NN];
__device__ int   g_ssrc[NE];
__device__ int   g_seid[NE];
__device__ float g_bnsum[2*HID];
__device__ float g_bnscale[HID];
__device__ float g_bnshift[HID];
__device__ float g_psum[NG*HID];
__device__ float g_pmax[NG*HID];
__device__ int   g_cnt[NG];
__device__ float g_gfeat[NG*3*HID];
__device__ float g_h1[NG*HID];
__device__ float g_h2[NG*(HID/2)];

// ---------------- init / CSR build ----------------
__global__ void k_zero_init() {
    int i = blockIdx.x * blockDim.x + threadIdx.x;
    int stride = gridDim.x * blockDim.x;
    for (int j = i; j < NN; j += stride) g_deg[j] = 0;
    for (int j = i; j < NG*HID; j += stride) { g_psum[j] = 0.f; g_pmax[j] = 0.f; }
    for (int j = i; j < NG; j += stride) g_cnt[j] = 0;
}

__global__ void k_hist(const int* __restrict__ ei) {
    int e = blockIdx.x * blockDim.x + threadIdx.x;
    if (e < NE) atomicAdd(&g_deg[ei[NE + e]], 1);
}

__global__ void k_scan() {
    __shared__ int s[1024];
    const int CH = (NN + 1023) / 1024;   // 49
    int tid = threadIdx.x;
    int start = tid * CH;
    int sum = 0;
    for (int i = 0; i < CH; i++) {
        int idx = start + i;
        if (idx < NN) sum += g_deg[idx];
    }
    s[tid] = sum;
    __syncthreads();
    for (int off = 1; off < 1024; off <<= 1) {
        int v = 0;
        if (tid >= off) v = s[tid - off];
        __syncthreads();
        if (tid >= off) s[tid] += v;
        __syncthreads();
    }
    int run = (tid == 0) ? 0 : s[tid - 1];
    for (int i = 0; i < CH; i++) {
        int idx = start + i;
        if (idx < NN) {
            g_offs[idx] = run;
            g_cursor[idx] = run;
            run += g_deg[idx];
        }
    }
    if (tid == 1023) g_offs[NN] = s[1023];
}

__global__ void k_scatter(const int* __restrict__ ei) {
    int e = blockIdx.x * blockDim.x + threadIdx.x;
    if (e < NE) {
        int s = ei[e];
        int d = ei[NE + e];
        int pos = atomicAdd(&g_cursor[d], 1);
        g_ssrc[pos] = s;
        g_seid[pos] = e;
    }
}

// ---------------- node encoder: h = relu(x @ enc_W + enc_b) ----------------
__global__ void k_enc(const float* __restrict__ x, const float* __restrict__ W,
                      const float* __restrict__ b) {
    __shared__ float sx[NDIM];
    int node = blockIdx.x;
    int c = threadIdx.x;
    if (c < NDIM) sx[c] = x[node * NDIM + c];
    __syncthreads();
    float a = b[c];
    #pragma unroll
    for (int k = 0; k < NDIM; k++) a += sx[k] * W[k * HID + c];
    g_h[(size_t)node * HID + c] = fmaxf(a, 0.f);
}

// ---------------- GINE aggregation: z0 = h + sum relu(h[src] + ea@W + b) ---
__global__ void k_aggregate(const float* __restrict__ edge_attr,
                            const float* __restrict__ eW,
                            const float* __restrict__ eb) {
    __shared__ float sW[EDIM * HID];
    __shared__ float sb[HID];
    for (int i = threadIdx.x; i < EDIM * HID; i += blockDim.x) sW[i] = eW[i];
    for (int i = threadIdx.x; i < HID; i += blockDim.x) sb[i] = eb[i];
    __syncthreads();
    int warp = threadIdx.x >> 5, lane = threadIdx.x & 31;
    int node = blockIdx.x * 8 + warp;
    if (node >= NN) return;
    float acc[8] = {0,0,0,0,0,0,0,0};
    int e0 = g_offs[node], e1 = g_offs[node + 1];
    for (int e = e0; e < e1; e++) {
        int src = g_ssrc[e];
        int eid = g_seid[e];
        float ea0 = edge_attr[eid*EDIM+0];
        float ea1 = edge_attr[eid*EDIM+1];
        float ea2 = edge_attr[eid*EDIM+2];
        float ea3 = edge_attr[eid*EDIM+3];
        float ea4 = edge_attr[eid*EDIM+4];
        const float* hrow = g_h + (size_t)src * HID;
        #pragma unroll
        for (int j = 0; j < 8; j++) {
            int c = lane + 32 * j;
            float m = hrow[c] + sb[c]
                    + ea0 * sW[c]
                    + ea1 * sW[HID + c]
                    + ea2 * sW[2*HID + c]
                    + ea3 * sW[3*HID + c]
                    + ea4 * sW[4*HID + c];
            acc[j] += fmaxf(m, 0.f);
        }
    }
    const float* hi = g_h + (size_t)node * HID;
    float* z = g_z0 + (size_t)node * HID;
    #pragma unroll
    for (int j = 0; j < 8; j++) {
        int c = lane + 32 * j;
        z[c] = hi[c] + acc[j];
    }
}

// ---------------- tiled fp32 GEMM: C = relu?(A[MxK] @ B[KxN] + bias) -------
template <int RELU>
__global__ void k_gemm(const float* __restrict__ A, const float* __restrict__ B,
                       const float* __restrict__ bias, float* __restrict__ C,
                       int M, int N, int K) {
    __shared__ float As[16][64];
    __shared__ float Bs[16][64];
    int tid = threadIdx.x;
    int tx = tid & 15, ty = tid >> 4;
    int bm = blockIdx.x * 64, bn = blockIdx.y * 64;
    int aR = tid >> 2;
    int aC = (tid & 3) * 4;
    int bR = tid >> 4;
    int bC = (tid & 15) * 4;
    int gArow = bm + aR;
    float acc[4][4] = {};
    for (int k0 = 0; k0 < K; k0 += 16) {
        float4 av = (gArow < M) ? *(const float4*)(A + (size_t)gArow * K + k0 + aC)
                                : make_float4(0.f, 0.f, 0.f, 0.f);
        As[aC + 0][aR] = av.x;
        As[aC + 1][aR] = av.y;
        As[aC + 2][aR] = av.z;
        As[aC + 3][aR] = av.w;
        *(float4*)&Bs[bR][bC] = *(const float4*)(B + (size_t)(k0 + bR) * N + bn + bC);
        __syncthreads();
        #pragma unroll
        for (int k = 0; k < 16; k++) {
            float4 a4 = *(const float4*)&As[k][ty * 4];
            float4 b4 = *(const float4*)&Bs[k][tx * 4];
            float ar[4] = {a4.x, a4.y, a4.z, a4.w};
            float br[4] = {b4.x, b4.y, b4.z, b4.w};
            #pragma unroll
            for (int i = 0; i < 4; i++)
                #pragma unroll
                for (int j = 0; j < 4; j++)
                    acc[i][j] += ar[i] * br[j];
        }
        __syncthreads();
    }
    #pragma unroll
    for (int i = 0; i < 4; i++) {
        int r = bm + ty * 4 + i;
        if (r < M) {
            #pragma unroll
            for (int j = 0; j < 4; j++) {
                int c = bn + tx * 4 + j;
                float v = acc[i][j] + bias[c];
                if (RELU) v = fmaxf(v, 0.f);
                C[(size_t)r * N + c] = v;
            }
        }
    }
}

// ---------------- batchnorm ----------------
__global__ void k_zero_bn() {
    g_bnsum[threadIdx.x] = 0.f;   // 512 threads
}

__global__ void k_bn_reduce(const float* __restrict__ z) {
    int c = threadIdx.x;                       // 256
    int r0 = blockIdx.x * 256;
    int r1 = min(r0 + 256, NN);
    float s = 0.f, s2 = 0.f;
    for (int r = r0; r < r1; r++) {
        float v = z[(size_t)r * HID + c];
        s += v; s2 += v * v;
    }
    atomicAdd(&g_bnsum[c], s);
    atomicAdd(&g_bnsum[HID + c], s2);
}

__global__ void k_bn_fin(const float* __restrict__ gamma, const float* __restrict__ beta) {
    int c = threadIdx.x;
    float mu = g_bnsum[c] * (1.f / NN);
    float var = g_bnsum[HID + c] * (1.f / NN) - mu * mu;
    float inv = rsqrtf(var + BN_EPS);
    float sc = inv * gamma[c];
    g_bnscale[c] = sc;
    g_bnshift[c] = beta[c] - mu * sc;
}

__global__ void k_bn_apply() {
    int i = blockIdx.x * blockDim.x + threadIdx.x;
    if (i < NN * HID) {
        int c = i & (HID - 1);
        float v = g_z2[i] * g_bnscale[c] + g_bnshift[c];
        g_h[i] = fmaxf(v, 0.f) + g_h[i];
    }
}

// ---------------- pooling (batch is sorted -> run-length accumulate) -------
__global__ void k_pool(const int* __restrict__ batch) {
    __shared__ int sb[128];
    int c = threadIdx.x;                 // 256 = channel
    int n0 = blockIdx.x * 128;
    int n1 = min(n0 + 128, NN);
    if (c < 128 && n0 + c < NN) sb[c] = batch[n0 + c];
    __syncthreads();
    float accS = 0.f, accM = 0.f;
    int cur = sb[0];
    int cnt = 0;
    for (int n = n0; n < n1; n++) {
        int g = sb[n - n0];
        if (g != cur) {
            atomicAdd(&g_psum[cur * HID + c], accS);
            atomicMax((int*)&g_pmax[cur * HID + c], __float_as_int(accM));
            if (c == 0) atomicAdd(&g_cnt[cur], cnt);
            accS = 0.f; accM = 0.f; cnt = 0; cur = g;
        }
        float v = g_h[(size_t)n * HID + c];
        accS += v;
        accM = fmaxf(accM, v);
        cnt++;
    }
    atomicAdd(&g_psum[cur * HID + c], accS);
    atomicMax((int*)&g_pmax[cur * HID + c], __float_as_int(accM));
    if (c == 0) atomicAdd(&g_cnt[cur], cnt);
}

__global__ void k_pool_fin() {
    int g = blockIdx.x, c = threadIdx.x;
    float s = g_psum[g * HID + c];
    float cnt = (float)max(g_cnt[g], 1);
    g_gfeat[g * 3 * HID + c]            = s / cnt;   // mean
    g_gfeat[g * 3 * HID + HID + c]      = s;         // sum
    g_gfeat[g * 3 * HID + 2 * HID + c]  = g_pmax[g * HID + c];  // max (h >= 0)
}

// ---------------- head final: out[g] = h2[g] . W3 + b3 ----------------
__global__ void k_final(const float* __restrict__ W3, const float* __restrict__ b3,
                        float* __restrict__ out) {
    __shared__ float red[128];
    int g = blockIdx.x, t = threadIdx.x;
    red[t] = g_h2[g * 128 + t] * W3[t];
    __syncthreads();
    for (int off = 64; off > 0; off >>= 1) {
        if (t < off) red[t] += red[t + off];
        __syncthreads();
    }
    if (t == 0) out[g] = red[0] + b3[0];
}

// ---------------- launch ----------------
extern "C" void kernel_launch(void* const* d_in, const int* in_sizes, int n_in,
                              void* d_out, int out_size) {
    const float* x     = (const float*)d_in[0];
    const int*   ei    = (const int*)  d_in[1];
    const float* eattr = (const float*)d_in[2];
    const int*   batch = (const int*)  d_in[3];
    const float* encW  = (const float*)d_in[4];
    const float* encb  = (const float*)d_in[5];
    const float* edgeW = (const float*)d_in[6];
    const float* edgeb = (const float*)d_in[7];
    const float* W1    = (const float*)d_in[8];
    const float* b1    = (const float*)d_in[9];
    const float* W2    = (const float*)d_in[10];
    const float* b2    = (const float*)d_in[11];
    const float* bng   = (const float*)d_in[12];
    const float* bnb   = (const float*)d_in[13];
    const float* hW1   = (const float*)d_in[14];
    const float* hb1   = (const float*)d_in[15];
    const float* hW2   = (const float*)d_in[16];
    const float* hb2   = (const float*)d_in[17];
    const float* hW3   = (const float*)d_in[18];
    const float* hb3   = (const float*)d_in[19];
    float* out = (float*)d_out;

    float *p_z0, *p_z1, *p_z2, *p_gf, *p_h1, *p_h2;
    cudaGetSymbolAddress((void**)&p_z0, g_z0);
    cudaGetSymbolAddress((void**)&p_z1, g_z1);
    cudaGetSymbolAddress((void**)&p_z2, g_z2);
    cudaGetSymbolAddress((void**)&p_gf, g_gfeat);
    cudaGetSymbolAddress((void**)&p_h1, g_h1);
    cudaGetSymbolAddress((void**)&p_h2, g_h2);

    // CSR build + init
    k_zero_init<<<512, 256>>>();
    k_hist<<<(NE + 255) / 256, 256>>>(ei);
    k_scan<<<1, 1024>>>();
    k_scatter<<<(NE + 255) / 256, 256>>>(ei);

    // encoder
    k_enc<<<NN, HID>>>(x, encW, encb);

    dim3 gemm_grid_big((NN + 63) / 64, HID / 64);
    for (int l = 0; l < NL; l++) {
        k_aggregate<<<(NN + 7) / 8, 256>>>(eattr, edgeW + l * EDIM * HID, edgeb + l * HID);
        k_gemm<1><<<gemm_grid_big, 256>>>(p_z0, W1 + l * HID * HID, b1 + l * HID, p_z1, NN, HID, HID);
        k_gemm<0><<<gemm_grid_big, 256>>>(p_z1, W2 + l * HID * HID, b2 + l * HID, p_z2, NN, HID, HID);
        k_zero_bn<<<1, 512>>>();
        k_bn_reduce<<<(NN + 255) / 256, 256>>>(p_z2);
        k_bn_fin<<<1, 256>>>(bng + l * HID, bnb + l * HID);
        k_bn_apply<<<(NN * HID + 255) / 256, 256>>>();
    }

    // pooling + head
    k_pool<<<(NN + 127) / 128, 256>>>(batch);
    k_pool_fin<<<NG, HID>>>();
    k_gemm<1><<<dim3(NG / 64, HID / 64), 256>>>(p_gf, hW1, hb1, p_h1, NG, HID, 3 * HID);
    k_gemm<1><<<dim3(NG / 64, (HID / 2) / 64), 256>>>(p_h1, hW2, hb2, p_h2, NG, HID / 2, HID);
    k_final<<<NG, 128>>>(hW3, hb3, out);
}

// round 2
// speedup vs baseline: 1.7759x; 1.7759x over previous
#include <cuda_runtime.h>
#include <math.h>

#define NN   50000
#define NE   300000
#define NDIM 11
#define EDIM 5
#define HID  256
#define NG   1024
#define NL   4
#define BN_EPS 1e-5f

// ---------------- scratch (device globals: allocation-free) ----------------
__device__ float g_h [NN*HID];
__device__ float g_z0[NN*HID];
__device__ float g_z1[NN*HID];
__device__ float g_z2[NN*HID];
__device__ int   g_deg[NN];
__device__ int   g_offs[NN+1];
__device__ int   g_cursor[NN];
__device__ int   g_ssrc[NE];
__device__ int   g_seid[NE];
__device__ float g_bnsum[2*HID];
__device__ float g_bnscale[HID];
__device__ float g_bnshift[HID];
__device__ float g_psum[NG*HID];
__device__ float g_pmax[NG*HID];
__device__ int   g_cnt[NG];
__device__ float g_gfeat[NG*3*HID];
__device__ float g_h1[NG*HID];
__device__ float g_h2[NG*(HID/2)];

// ---------------- init / CSR build ----------------
__global__ void k_zero_init() {
    int i = blockIdx.x * blockDim.x + threadIdx.x;
    int stride = gridDim.x * blockDim.x;
    for (int j = i; j < NN; j += stride) g_deg[j] = 0;
    for (int j = i; j < NG*HID; j += stride) { g_psum[j] = 0.f; g_pmax[j] = 0.f; }
    for (int j = i; j < NG; j += stride) g_cnt[j] = 0;
}

__global__ void k_hist(const int* __restrict__ ei) {
    int e = blockIdx.x * blockDim.x + threadIdx.x;
    if (e < NE) atomicAdd(&g_deg[ei[NE + e]], 1);
}

__global__ void k_scan() {
    __shared__ int s[1024];
    const int CH = (NN + 1023) / 1024;
    int tid = threadIdx.x;
    int start = tid * CH;
    int sum = 0;
    for (int i = 0; i < CH; i++) {
        int idx = start + i;
        if (idx < NN) sum += g_deg[idx];
    }
    s[tid] = sum;
    __syncthreads();
    for (int off = 1; off < 1024; off <<= 1) {
        int v = 0;
        if (tid >= off) v = s[tid - off];
        __syncthreads();
        if (tid >= off) s[tid] += v;
        __syncthreads();
    }
    int run = (tid == 0) ? 0 : s[tid - 1];
    for (int i = 0; i < CH; i++) {
        int idx = start + i;
        if (idx < NN) {
            g_offs[idx] = run;
            g_cursor[idx] = run;
            run += g_deg[idx];
        }
    }
    if (tid == 1023) g_offs[NN] = s[1023];
}

__global__ void k_scatter(const int* __restrict__ ei) {
    int e = blockIdx.x * blockDim.x + threadIdx.x;
    if (e < NE) {
        int s = ei[e];
        int d = ei[NE + e];
        int pos = atomicAdd(&g_cursor[d], 1);
        g_ssrc[pos] = s;
        g_seid[pos] = e;
    }
}

// ---------------- node encoder ----------------
__global__ void k_enc(const float* __restrict__ x, const float* __restrict__ W,
                      const float* __restrict__ b) {
    __shared__ float sx[NDIM];
    int node = blockIdx.x;
    int c = threadIdx.x;
    if (c < NDIM) sx[c] = x[node * NDIM + c];
    __syncthreads();
    float a = b[c];
    #pragma unroll
    for (int k = 0; k < NDIM; k++) a += sx[k] * W[k * HID + c];
    g_h[(size_t)node * HID + c] = fmaxf(a, 0.f);
}

// ---------------- GINE aggregation ----------------
__global__ void k_aggregate(const float* __restrict__ edge_attr,
                            const float* __restrict__ eW,
                            const float* __restrict__ eb) {
    __shared__ float sW[EDIM * HID];
    __shared__ float sb[HID];
    for (int i = threadIdx.x; i < EDIM * HID; i += blockDim.x) sW[i] = eW[i];
    for (int i = threadIdx.x; i < HID; i += blockDim.x) sb[i] = eb[i];
    __syncthreads();
    int warp = threadIdx.x >> 5, lane = threadIdx.x & 31;
    int node = blockIdx.x * 8 + warp;
    if (node >= NN) return;
    float acc[8] = {0,0,0,0,0,0,0,0};
    int e0 = g_offs[node], e1 = g_offs[node + 1];
    for (int e = e0; e < e1; e++) {
        int src = g_ssrc[e];
        int eid = g_seid[e];
        float ea0 = edge_attr[eid*EDIM+0];
        float ea1 = edge_attr[eid*EDIM+1];
        float ea2 = edge_attr[eid*EDIM+2];
        float ea3 = edge_attr[eid*EDIM+3];
        float ea4 = edge_attr[eid*EDIM+4];
        const float* hrow = g_h + (size_t)src * HID;
        #pragma unroll
        for (int j = 0; j < 8; j++) {
            int c = lane + 32 * j;
            float m = hrow[c] + sb[c]
                    + ea0 * sW[c]
                    + ea1 * sW[HID + c]
                    + ea2 * sW[2*HID + c]
                    + ea3 * sW[3*HID + c]
                    + ea4 * sW[4*HID + c];
            acc[j] += fmaxf(m, 0.f);
        }
    }
    const float* hi = g_h + (size_t)node * HID;
    float* z = g_z0 + (size_t)node * HID;
    #pragma unroll
    for (int j = 0; j < 8; j++) {
        int c = lane + 32 * j;
        z[c] = hi[c] + acc[j];
    }
}

// ---------------- TF32 tensor-core GEMM (N=K=256 fixed) ----------------
// C[M,256] = relu?(A[M,256] @ B[256,256] + bias)
// block tile 128x128, 8 warps (2x4), warp tile 64x32, mma m16n8k8 tf32.

__device__ __forceinline__ unsigned f2tf32(float f) {
    unsigned u;
    asm("cvt.rna.tf32.f32 %0, %1;" : "=r"(u) : "f"(f));
    return u;
}

__device__ __forceinline__ void cp_async16(void* smem, const void* gmem, int srcsz) {
    unsigned saddr = (unsigned)__cvta_generic_to_shared(smem);
    asm volatile("cp.async.ca.shared.global [%0], [%1], 16, %2;\n"
                 :: "r"(saddr), "l"(gmem), "r"(srcsz));
}
__device__ __forceinline__ void cp_commit() {
    asm volatile("cp.async.commit_group;\n");
}
template <int N>
__device__ __forceinline__ void cp_wait() {
    asm volatile("cp.async.wait_group %0;\n" :: "n"(N));
}

#define KC 16
#define A_STRIDE 20     // 16 + 4 pad : conflict-free fragment reads
#define B_STRIDE 136    // 128 + 8 pad

template <int RELU>
__global__ void __launch_bounds__(256, 2)
k_gemm_tc(const float* __restrict__ A, const float* __restrict__ B,
          const float* __restrict__ bias, float* __restrict__ C, int M) {
    __shared__ float A_s[2][128 * A_STRIDE];
    __shared__ float B_s[2][KC * B_STRIDE];

    const int tid = threadIdx.x;
    const int wid = tid >> 5;
    const int lane = tid & 31;
    const int g = lane >> 2;     // 0..7
    const int t = lane & 3;      // 0..3
    const int warpRow = wid >> 2;  // 0..1 -> 64 rows
    const int warpCol = wid & 3;   // 0..3 -> 32 cols
    const int bm = blockIdx.x * 128;
    const int bn = blockIdx.y * 128;

    float acc[4][4][4];
    #pragma unroll
    for (int i = 0; i < 4; i++)
        #pragma unroll
        for (int j = 0; j < 4; j++)
            #pragma unroll
            for (int k = 0; k < 4; k++) acc[i][j][k] = 0.f;

    // stage loader: 512 x 16B for A, 512 x 16B for B, 256 threads -> 2 each
    auto load_stage = [&](int buf, int k0) {
        #pragma unroll
        for (int rep = 0; rep < 2; rep++) {
            int i = tid + rep * 256;
            // A: row = i>>2 (0..127), seg = i&3 (4 floats each)
            {
                int row = i >> 2, seg = i & 3;
                int gr = bm + row;
                cp_async16(&A_s[buf][row * A_STRIDE + seg * 4],
                           A + (size_t)gr * 256 + k0 + seg * 4,
                           gr < M ? 16 : 0);
            }
            // B: row = i>>5 (0..15), seg = i&31
            {
                int row = i >> 5, seg = i & 31;
                cp_async16(&B_s[buf][row * B_STRIDE + seg * 4],
                           B + (size_t)(k0 + row) * 256 + bn + seg * 4, 16);
            }
        }
        cp_commit();
    };

    const int NI = 256 / KC;  // 16
    load_stage(0, 0);

    for (int it = 0; it < NI; it++) {
        int buf = it & 1;
        if (it + 1 < NI) load_stage(buf ^ 1, (it + 1) * KC);
        if (it + 1 < NI) cp_wait<1>(); else cp_wait<0>();
        __syncthreads();

        #pragma unroll
        for (int kk = 0; kk < KC / 8; kk++) {
            const int kb = kk * 8;
            unsigned af[4][4];
            unsigned bf[4][2];
            #pragma unroll
            for (int mt = 0; mt < 4; mt++) {
                const float* As = &A_s[buf][(warpRow * 64 + mt * 16 + g) * A_STRIDE + kb + t];
                af[mt][0] = f2tf32(As[0]);
                af[mt][1] = f2tf32(As[8 * A_STRIDE]);
                af[mt][2] = f2tf32(As[4]);
                af[mt][3] = f2tf32(As[8 * A_STRIDE + 4]);
            }
            #pragma unroll
            for (int nt = 0; nt < 4; nt++) {
                const float* Bs = &B_s[buf][(kb + t) * B_STRIDE + warpCol * 32 + nt * 8 + g];
                bf[nt][0] = f2tf32(Bs[0]);
                bf[nt][1] = f2tf32(Bs[4 * B_STRIDE]);
            }
            #pragma unroll
            for (int mt = 0; mt < 4; mt++)
                #pragma unroll
                for (int nt = 0; nt < 4; nt++) {
                    asm volatile(
                        "mma.sync.aligned.m16n8k8.row.col.f32.tf32.tf32.f32 "
                        "{%0,%1,%2,%3}, {%4,%5,%6,%7}, {%8,%9}, {%0,%1,%2,%3};\n"
                        : "+f"(acc[mt][nt][0]), "+f"(acc[mt][nt][1]),
                          "+f"(acc[mt][nt][2]), "+f"(acc[mt][nt][3])
                        : "r"(af[mt][0]), "r"(af[mt][1]), "r"(af[mt][2]), "r"(af[mt][3]),
                          "r"(bf[nt][0]), "r"(bf[nt][1]));
                }
        }
        __syncthreads();
    }

    // epilogue: bias (+relu), write float2 pairs
    #pragma unroll
    for (int mt = 0; mt < 4; mt++) {
        int r0 = bm + warpRow * 64 + mt * 16 + g;
        int r1 = r0 + 8;
        #pragma unroll
        for (int nt = 0; nt < 4; nt++) {
            int c = bn + warpCol * 32 + nt * 8 + 2 * t;
            float b0 = bias[c], b1 = bias[c + 1];
            float v0 = acc[mt][nt][0] + b0;
            float v1 = acc[mt][nt][1] + b1;
            float v2 = acc[mt][nt][2] + b0;
            float v3 = acc[mt][nt][3] + b1;
            if (RELU) {
                v0 = fmaxf(v0, 0.f); v1 = fmaxf(v1, 0.f);
                v2 = fmaxf(v2, 0.f); v3 = fmaxf(v3, 0.f);
            }
            if (r0 < M) *(float2*)(C + (size_t)r0 * 256 + c) = make_float2(v0, v1);
            if (r1 < M) *(float2*)(C + (size_t)r1 * 256 + c) = make_float2(v2, v3);
        }
    }
}

// ---------------- fp32 SIMT GEMM (for head, small) ----------------
template <int RELU>
__global__ void k_gemm(const float* __restrict__ A, const float* __restrict__ B,
                       const float* __restrict__ bias, float* __restrict__ C,
                       int M, int N, int K) {
    __shared__ float As[16][64];
    __shared__ float Bs[16][64];
    int tid = threadIdx.x;
    int tx = tid & 15, ty = tid >> 4;
    int bm = blockIdx.x * 64, bn = blockIdx.y * 64;
    int aR = tid >> 2;
    int aC = (tid & 3) * 4;
    int bR = tid >> 4;
    int bC = (tid & 15) * 4;
    int gArow = bm + aR;
    float acc[4][4] = {};
    for (int k0 = 0; k0 < K; k0 += 16) {
        float4 av = (gArow < M) ? *(const float4*)(A + (size_t)gArow * K + k0 + aC)
                                : make_float4(0.f, 0.f, 0.f, 0.f);
        As[aC + 0][aR] = av.x;
        As[aC + 1][aR] = av.y;
        As[aC + 2][aR] = av.z;
        As[aC + 3][aR] = av.w;
        *(float4*)&Bs[bR][bC] = *(const float4*)(B + (size_t)(k0 + bR) * N + bn + bC);
        __syncthreads();
        #pragma unroll
        for (int k = 0; k < 16; k++) {
            float4 a4 = *(const float4*)&As[k][ty * 4];
            float4 b4 = *(const float4*)&Bs[k][tx * 4];
            float ar[4] = {a4.x, a4.y, a4.z, a4.w};
            float br[4] = {b4.x, b4.y, b4.z, b4.w};
            #pragma unroll
            for (int i = 0; i < 4; i++)
                #pragma unroll
                for (int j = 0; j < 4; j++)
                    acc[i][j] += ar[i] * br[j];
        }
        __syncthreads();
    }
    #pragma unroll
    for (int i = 0; i < 4; i++) {
        int r = bm + ty * 4 + i;
        if (r < M) {
            #pragma unroll
            for (int j = 0; j < 4; j++) {
                int c = bn + tx * 4 + j;
                float v = acc[i][j] + bias[c];
                if (RELU) v = fmaxf(v, 0.f);
                C[(size_t)r * N + c] = v;
            }
        }
    }
}

// ---------------- batchnorm ----------------
__global__ void k_zero_bn() {
    g_bnsum[threadIdx.x] = 0.f;   // 512 threads
}

__global__ void k_bn_reduce(const float* __restrict__ z) {
    int c = threadIdx.x;
    int r0 = blockIdx.x * 256;
    int r1 = min(r0 + 256, NN);
    float s = 0.f, s2 = 0.f;
    for (int r = r0; r < r1; r++) {
        float v = z[(size_t)r * HID + c];
        s += v; s2 += v * v;
    }
    atomicAdd(&g_bnsum[c], s);
    atomicAdd(&g_bnsum[HID + c], s2);
}

__global__ void k_bn_fin(const float* __restrict__ gamma, const float* __restrict__ beta) {
    int c = threadIdx.x;
    float mu = g_bnsum[c] * (1.f / NN);
    float var = g_bnsum[HID + c] * (1.f / NN) - mu * mu;
    float inv = rsqrtf(var + BN_EPS);
    float sc = inv * gamma[c];
    g_bnscale[c] = sc;
    g_bnshift[c] = beta[c] - mu * sc;
}

__global__ void k_bn_apply() {
    int i = blockIdx.x * blockDim.x + threadIdx.x;
    if (i < NN * HID) {
        int c = i & (HID - 1);
        float v = g_z2[i] * g_bnscale[c] + g_bnshift[c];
        g_h[i] = fmaxf(v, 0.f) + g_h[i];
    }
}

// ---------------- pooling ----------------
__global__ void k_pool(const int* __restrict__ batch) {
    __shared__ int sb[128];
    int c = threadIdx.x;
    int n0 = blockIdx.x * 128;
    int n1 = min(n0 + 128, NN);
    if (c < 128 && n0 + c < NN) sb[c] = batch[n0 + c];
    __syncthreads();
    float accS = 0.f, accM = 0.f;
    int cur = sb[0];
    int cnt = 0;
    for (int n = n0; n < n1; n++) {
        int gg = sb[n - n0];
        if (gg != cur) {
            atomicAdd(&g_psum[cur * HID + c], accS);
            atomicMax((int*)&g_pmax[cur * HID + c], __float_as_int(accM));
            if (c == 0) atomicAdd(&g_cnt[cur], cnt);
            accS = 0.f; accM = 0.f; cnt = 0; cur = gg;
        }
        float v = g_h[(size_t)n * HID + c];
        accS += v;
        accM = fmaxf(accM, v);
        cnt++;
    }
    atomicAdd(&g_psum[cur * HID + c], accS);
    atomicMax((int*)&g_pmax[cur * HID + c], __float_as_int(accM));
    if (c == 0) atomicAdd(&g_cnt[cur], cnt);
}

__global__ void k_pool_fin() {
    int g = blockIdx.x, c = threadIdx.x;
    float s = g_psum[g * HID + c];
    float cnt = (float)max(g_cnt[g], 1);
    g_gfeat[g * 3 * HID + c]            = s / cnt;
    g_gfeat[g * 3 * HID + HID + c]      = s;
    g_gfeat[g * 3 * HID + 2 * HID + c]  = g_pmax[g * HID + c];
}

// ---------------- head final ----------------
__global__ void k_final(const float* __restrict__ W3, const float* __restrict__ b3,
                        float* __restrict__ out) {
    __shared__ float red[128];
    int g = blockIdx.x, t = threadIdx.x;
    red[t] = g_h2[g * 128 + t] * W3[t];
    __syncthreads();
    for (int off = 64; off > 0; off >>= 1) {
        if (t < off) red[t] += red[t + off];
        __syncthreads();
    }
    if (t == 0) out[g] = red[0] + b3[0];
}

// ---------------- launch ----------------
extern "C" void kernel_launch(void* const* d_in, const int* in_sizes, int n_in,
                              void* d_out, int out_size) {
    const float* x     = (const float*)d_in[0];
    const int*   ei    = (const int*)  d_in[1];
    const float* eattr = (const float*)d_in[2];
    const int*   batch = (const int*)  d_in[3];
    const float* encW  = (const float*)d_in[4];
    const float* encb  = (const float*)d_in[5];
    const float* edgeW = (const float*)d_in[6];
    const float* edgeb = (const float*)d_in[7];
    const float* W1    = (const float*)d_in[8];
    const float* b1    = (const float*)d_in[9];
    const float* W2    = (const float*)d_in[10];
    const float* b2    = (const float*)d_in[11];
    const float* bng   = (const float*)d_in[12];
    const float* bnb   = (const float*)d_in[13];
    const float* hW1   = (const float*)d_in[14];
    const float* hb1   = (const float*)d_in[15];
    const float* hW2   = (const float*)d_in[16];
    const float* hb2   = (const float*)d_in[17];
    const float* hW3   = (const float*)d_in[18];
    const float* hb3   = (const float*)d_in[19];
    float* out = (float*)d_out;

    float *p_z0, *p_z1, *p_z2, *p_gf, *p_h1, *p_h2;
    cudaGetSymbolAddress((void**)&p_z0, g_z0);
    cudaGetSymbolAddress((void**)&p_z1, g_z1);
    cudaGetSymbolAddress((void**)&p_z2, g_z2);
    cudaGetSymbolAddress((void**)&p_gf, g_gfeat);
    cudaGetSymbolAddress((void**)&p_h1, g_h1);
    cudaGetSymbolAddress((void**)&p_h2, g_h2);

    // CSR build + init
    k_zero_init<<<512, 256>>>();
    k_hist<<<(NE + 255) / 256, 256>>>(ei);
    k_scan<<<1, 1024>>>();
    k_scatter<<<(NE + 255) / 256, 256>>>(ei);

    // encoder
    k_enc<<<NN, HID>>>(x, encW, encb);

    dim3 tc_grid((NN + 127) / 128, 2);
    for (int l = 0; l < NL; l++) {
        k_aggregate<<<(NN + 7) / 8, 256>>>(eattr, edgeW + l * EDIM * HID, edgeb + l * HID);
        k_gemm_tc<1><<<tc_grid, 256>>>(p_z0, W1 + l * HID * HID, b1 + l * HID, p_z1, NN);
        k_gemm_tc<0><<<tc_grid, 256>>>(p_z1, W2 + l * HID * HID, b2 + l * HID, p_z2, NN);
        k_zero_bn<<<1, 512>>>();
        k_bn_reduce<<<(NN + 255) / 256, 256>>>(p_z2);
        k_bn_fin<<<1, 256>>>(bng + l * HID, bnb + l * HID);
        k_bn_apply<<<(NN * HID + 255) / 256, 256>>>();
    }

    // pooling + head
    k_pool<<<(NN + 127) / 128, 256>>>(batch);
    k_pool_fin<<<NG, HID>>>();
    k_gemm<1><<<dim3(NG / 64, HID / 64), 256>>>(p_gf, hW1, hb1, p_h1, NG, HID, 3 * HID);
    k_gemm<1><<<dim3(NG / 64, (HID / 2) / 64), 256>>>(p_h1, hW2, hb2, p_h2, NG, HID / 2, HID);
    k_final<<<NG, 128>>>(hW3, hb3, out);
}

// round 4
// speedup vs baseline: 2.1357x; 1.2026x over previous
#include <cuda_runtime.h>
#include <math.h>
#include <stdint.h>

#define NN    50000
#define NNPAD 50048   // 391 * 128
#define NE    300000
#define NDIM  11
#define EDIM  5
#define HID   256
#define NG    1024
#define NL    4
#define BN_EPS 1e-5f

// ---------------- scratch (device globals: allocation-free) ----------------
__device__ float g_h  [NN*HID];
__device__ float g_z2 [NN*HID];
__device__ float g_a0f[NNPAD*HID];   // GEMM1 A, fragment order, tf32-rounded
__device__ float g_a1f[NNPAD*HID];   // GEMM2 A (=GEMM1 out), fragment order
__device__ float g_wf [8*HID*HID];   // weights, fragment order, tf32-rounded
__device__ int   g_deg[NN];
__device__ int   g_offs[NN+1];
__device__ int   g_cursor[NN];
__device__ int   g_ssrc[NE];
__device__ int   g_seid[NE];
__device__ float g_bnsum[2*HID];
__device__ float g_bnscale[HID];
__device__ float g_bnshift[HID];
__device__ float g_psum[NG*HID];
__device__ float g_pmax[NG*HID];
__device__ int   g_cnt[NG];
__device__ float g_gfeat[NG*3*HID];
__device__ float g_h1[NG*HID];
__device__ float g_h2[NG*(HID/2)];

// ---------------- helpers ----------------
__device__ __forceinline__ unsigned f2tf32(float f) {
    unsigned u;
    asm("cvt.rna.tf32.f32 %0, %1;" : "=r"(u) : "f"(f));
    return u;
}
__device__ __forceinline__ float tf32r(float f) { return __uint_as_float(f2tf32(f)); }

__device__ __forceinline__ void cp16(void* s, const void* g) {
    unsigned sa = (unsigned)__cvta_generic_to_shared(s);
    asm volatile("cp.async.ca.shared.global [%0], [%1], 16;\n" :: "r"(sa), "l"(g));
}

// ---------------- init / CSR build ----------------
__global__ void k_zero_init() {
    int i = blockIdx.x * blockDim.x + threadIdx.x;
    int stride = gridDim.x * blockDim.x;
    for (int j = i; j < NN; j += stride) g_deg[j] = 0;
    for (int j = i; j < NG*HID; j += stride) { g_psum[j] = 0.f; g_pmax[j] = 0.f; }
    for (int j = i; j < NG; j += stride) g_cnt[j] = 0;
    for (int j = i; j < 2*HID; j += stride) g_bnsum[j] = 0.f;
}

__global__ void k_hist(const int* __restrict__ ei) {
    int e = blockIdx.x * blockDim.x + threadIdx.x;
    if (e < NE) atomicAdd(&g_deg[ei[NE + e]], 1);
}

__global__ void k_scan() {
    __shared__ int s[1024];
    const int CH = (NN + 1023) / 1024;
    int tid = threadIdx.x;
    int start = tid * CH;
    int sum = 0;
    for (int i = 0; i < CH; i++) {
        int idx = start + i;
        if (idx < NN) sum += g_deg[idx];
    }
    s[tid] = sum;
    __syncthreads();
    for (int off = 1; off < 1024; off <<= 1) {
        int v = 0;
        if (tid >= off) v = s[tid - off];
        __syncthreads();
        if (tid >= off) s[tid] += v;
        __syncthreads();
    }
    int run = (tid == 0) ? 0 : s[tid - 1];
    for (int i = 0; i < CH; i++) {
        int idx = start + i;
        if (idx < NN) {
            g_offs[idx] = run;
            g_cursor[idx] = run;
            run += g_deg[idx];
        }
    }
    if (tid == 1023) g_offs[NN] = s[1023];
}

__global__ void k_scatter(const int* __restrict__ ei) {
    int e = blockIdx.x * blockDim.x + threadIdx.x;
    if (e < NE) {
        int s = ei[e];
        int d = ei[NE + e];
        int pos = atomicAdd(&g_cursor[d], 1);
        g_ssrc[pos] = s;
        g_seid[pos] = e;
    }
}

// ---------------- weight prep: fragment order + tf32 round ----------------
// frag[N8][S][lane(g*4+t)] float2 = {W[S*8+t][n], W[S*8+t+4][n]}, n = N8*8+g
__global__ void k_wprep(const float* __restrict__ W1, const float* __restrict__ W2) {
    int mat = blockIdx.x;           // 0..7 = layer*2 + (0:W1, 1:W2)
    int l = mat >> 1;
    const float* W = (mat & 1) ? (W2 + l * HID * HID) : (W1 + l * HID * HID);
    float2* F2 = (float2*)(g_wf + (size_t)mat * HID * HID);
    int n = threadIdx.x;            // 256
    int n8 = n >> 3, g = n & 7;
    for (int S = 0; S < 32; S++) {
        float w[8];
        #pragma unroll
        for (int j = 0; j < 8; j++) w[j] = tf32r(W[(S * 8 + j) * HID + n]);
        int base = (n8 * 32 + S) * 32 + g * 4;
        *(float4*)&F2[base]     = make_float4(w[0], w[4], w[1], w[5]);
        *(float4*)&F2[base + 2] = make_float4(w[2], w[6], w[3], w[7]);
    }
}

// ---------------- node encoder ----------------
__global__ void k_enc(const float* __restrict__ x, const float* __restrict__ W,
                      const float* __restrict__ b) {
    __shared__ float sx[NDIM];
    int node = blockIdx.x;
    int c = threadIdx.x;
    if (c < NDIM) sx[c] = x[node * NDIM + c];
    __syncthreads();
    float a = b[c];
    #pragma unroll
    for (int k = 0; k < NDIM; k++) a += sx[k] * W[k * HID + c];
    g_h[(size_t)node * HID + c] = fmaxf(a, 0.f);
}

// ---------------- GINE aggregation -> fragment-order tf32 A ----------------
// lane l owns channels c = l*8 + j (j=0..7) = k-slice S=l of the next GEMM.
__global__ void k_aggregate(const float* __restrict__ edge_attr,
                            const float* __restrict__ eW,
                            const float* __restrict__ eb,
                            float* __restrict__ Afrag) {
    __shared__ float sWt[EDIM * 256];   // transposed: [d][ (c&7)*32 + (c>>3) ]
    for (int i = threadIdx.x; i < EDIM * 256; i += 256) {
        int d = i >> 8, c = i & 255;
        sWt[d * 256 + ((c & 7) * 32 + (c >> 3))] = eW[i];
    }
    __syncthreads();
    int warp = threadIdx.x >> 5, l = threadIdx.x & 31;
    int node = blockIdx.x * 8 + warp;
    if (node >= NN) return;

    float ebr[8];
    {
        float4 e0 = *(const float4*)(eb + l * 8);
        float4 e1 = *(const float4*)(eb + l * 8 + 4);
        ebr[0]=e0.x; ebr[1]=e0.y; ebr[2]=e0.z; ebr[3]=e0.w;
        ebr[4]=e1.x; ebr[5]=e1.y; ebr[6]=e1.z; ebr[7]=e1.w;
    }
    float acc[8] = {0,0,0,0,0,0,0,0};
    int e0i = g_offs[node], e1i = g_offs[node + 1];
    for (int e = e0i; e < e1i; e++) {
        int src = g_ssrc[e];
        int eid = g_seid[e];
        float ea0 = edge_attr[eid*EDIM+0];
        float ea1 = edge_attr[eid*EDIM+1];
        float ea2 = edge_attr[eid*EDIM+2];
        float ea3 = edge_attr[eid*EDIM+3];
        float ea4 = edge_attr[eid*EDIM+4];
        const float* hrow = g_h + (size_t)src * HID + l * 8;
        float4 h0 = *(const float4*)hrow;
        float4 h1 = *(const float4*)(hrow + 4);
        float hr[8] = {h0.x,h0.y,h0.z,h0.w,h1.x,h1.y,h1.z,h1.w};
        #pragma unroll
        for (int j = 0; j < 8; j++) {
            float m = hr[j] + ebr[j]
                    + ea0 * sWt[            j*32 + l]
                    + ea1 * sWt[  256 +     j*32 + l]
                    + ea2 * sWt[  512 +     j*32 + l]
                    + ea3 * sWt[  768 +     j*32 + l]
                    + ea4 * sWt[ 1024 +     j*32 + l];
            acc[j] += fmaxf(m, 0.f);
        }
    }
    const float* hi = g_h + (size_t)node * HID + l * 8;
    float4 v0 = *(const float4*)hi;
    float4 v1 = *(const float4*)(hi + 4);
    float hv[8] = {v0.x,v0.y,v0.z,v0.w,v1.x,v1.y,v1.z,v1.w};
    float rv[8];
    #pragma unroll
    for (int j = 0; j < 8; j++) rv[j] = tf32r(hv[j] + acc[j]);

    int Rg = node >> 4, h = (node >> 3) & 1, g = node & 7;
    float2* A2 = (float2*)Afrag;
    size_t base = (((size_t)Rg * 32 + l) * 2 + h) * 32 + g * 4;
    *(float4*)&A2[base]     = make_float4(rv[0], rv[4], rv[1], rv[5]);
    *(float4*)&A2[base + 2] = make_float4(rv[2], rv[6], rv[3], rv[7]);
}

// ---------------- tf32 fragment-order tensor GEMM ----------------
// C[M,256] = A[M,256] @ W.  Block tile 128x128, 8 warps (2x4), warp 64x32.
// KC=32 per stage, double-buffered cp.async.
// FRAG_OUT=1: relu(acc+bias) -> tf32 round -> fragment-order write (for next GEMM)
// FRAG_OUT=0: acc+bias -> plain row-major f32 write
#define GEMM_SMEM 65536
template <int FRAG_OUT>
__global__ void __launch_bounds__(256, 2)
k_gemm_f(const float* __restrict__ Af, const float* __restrict__ Bf,
         const float* __restrict__ bias, float* __restrict__ Cout) {
    extern __shared__ char sm[];
    const int tid = threadIdx.x;
    const int wid = tid >> 5, lane = tid & 31;
    const int g = lane >> 2, t = lane & 3;
    const int warpRow = wid >> 2;      // 0..1
    const int wc = wid & 3;            // 0..3
    const int bm = blockIdx.x * 128;
    const int bn = blockIdx.y * 128;
    const int Rbase  = bm >> 4;        // 8 row-tiles
    const int N8base = bn >> 3;        // 16 col-tiles

    float acc[4][4][4];
    #pragma unroll
    for (int i = 0; i < 4; i++)
        #pragma unroll
        for (int j = 0; j < 4; j++) {
            acc[i][j][0]=0.f; acc[i][j][1]=0.f; acc[i][j][2]=0.f; acc[i][j][3]=0.f;
        }

    auto load_stage = [&](int buf, int st) {
        char* sA = sm + buf * 32768;
        char* sB = sA + 16384;
        const int Sbase = st * 4;
        #pragma unroll
        for (int i = 0; i < 4; i++) {
            int ch = tid + i * 256;
            {   // A: 1024 chunks of 16B
                int r = ch >> 7, inner = ch & 127;
                const float* gp = Af + ((size_t)(Rbase + r) * 32 + Sbase) * 128 + inner * 4;
                cp16(sA + r * 2048 + inner * 16, gp);
            }
            {   // B: 1024 chunks of 16B
                int n8 = ch >> 6, inner = ch & 63;
                const float* gp = Bf + ((size_t)(N8base + n8) * 32 + Sbase) * 64 + inner * 4;
                cp16(sB + n8 * 1024 + inner * 16, gp);
            }
        }
        asm volatile("cp.async.commit_group;");
    };

    load_stage(0, 0);
    const int NSTAGE = 8;
    for (int st = 0; st < NSTAGE; st++) {
        int buf = st & 1;
        if (st + 1 < NSTAGE) {
            load_stage(buf ^ 1, st + 1);
            asm volatile("cp.async.wait_group 1;");
        } else {
            asm volatile("cp.async.wait_group 0;");
        }
        __syncthreads();

        const float2* sA2 = (const float2*)(sm + buf * 32768);
        const float2* sB2 = (const float2*)(sm + buf * 32768 + 16384);
        #pragma unroll
        for (int Sl = 0; Sl < 4; Sl++) {
            unsigned af[4][4];
            unsigned bf[4][2];
            #pragma unroll
            for (int mt = 0; mt < 4; mt++) {
                float2 h0 = sA2[((warpRow * 4 + mt) * 4 + Sl) * 64 + lane];
                float2 h1 = sA2[((warpRow * 4 + mt) * 4 + Sl) * 64 + 32 + lane];
                af[mt][0] = __float_as_uint(h0.x);
                af[mt][1] = __float_as_uint(h1.x);
                af[mt][2] = __float_as_uint(h0.y);
                af[mt][3] = __float_as_uint(h1.y);
            }
            #pragma unroll
            for (int nt = 0; nt < 4; nt++) {
                float2 bb = sB2[((wc * 4 + nt) * 4 + Sl) * 32 + lane];
                bf[nt][0] = __float_as_uint(bb.x);
                bf[nt][1] = __float_as_uint(bb.y);
            }
            #pragma unroll
            for (int mt = 0; mt < 4; mt++)
                #pragma unroll
                for (int nt = 0; nt < 4; nt++) {
                    asm volatile(
                        "mma.sync.aligned.m16n8k8.row.col.f32.tf32.tf32.f32 "
                        "{%0,%1,%2,%3}, {%4,%5,%6,%7}, {%8,%9}, {%0,%1,%2,%3};\n"
                        : "+f"(acc[mt][nt][0]), "+f"(acc[mt][nt][1]),
                          "+f"(acc[mt][nt][2]), "+f"(acc[mt][nt][3])
                        : "r"(af[mt][0]), "r"(af[mt][1]), "r"(af[mt][2]), "r"(af[mt][3]),
                          "r"(bf[nt][0]), "r"(bf[nt][1]));
                }
        }
        __syncthreads();
    }

    // ---------------- epilogue ----------------
    const unsigned FULL = 0xffffffffu;
    #pragma unroll
    for (int mt = 0; mt < 4; mt++) {
        int r0 = bm + warpRow * 64 + mt * 16 + g;
        int r1 = r0 + 8;
        #pragma unroll
        for (int nt = 0; nt < 4; nt++) {
            int cbase = bn + wc * 32 + nt * 8;
            int c0 = cbase + 2 * t;
            float v0 = acc[mt][nt][0] + bias[c0];
            float v1 = acc[mt][nt][1] + bias[c0 + 1];
            float v2 = acc[mt][nt][2] + bias[c0];
            float v3 = acc[mt][nt][3] + bias[c0 + 1];
            if (FRAG_OUT) {
                v0 = tf32r(fmaxf(v0, 0.f));
                v1 = tf32r(fmaxf(v1, 0.f));
                v2 = tf32r(fmaxf(v2, 0.f));
                v3 = tf32r(fmaxf(v3, 0.f));
                int s0 = (lane & ~3) | (t >> 1);
                int s1 = s0 | 2;
                float A0 = __shfl_sync(FULL, v0, s0), A1 = __shfl_sync(FULL, v1, s0);
                float B0 = __shfl_sync(FULL, v0, s1), B1 = __shfl_sync(FULL, v1, s1);
                float C0 = __shfl_sync(FULL, v2, s0), C1 = __shfl_sync(FULL, v3, s0);
                float D0 = __shfl_sync(FULL, v2, s1), D1 = __shfl_sync(FULL, v3, s1);
                float x0 = (t & 1) ? A1 : A0;
                float x1 = (t & 1) ? B1 : B0;
                float x2 = (t & 1) ? C1 : C0;
                float x3 = (t & 1) ? D1 : D0;
                int Rg = r0 >> 4;
                int S = cbase >> 3;
                float2* C2 = (float2*)Cout;
                size_t base = (((size_t)Rg * 32 + S) * 2) * 32 + g * 4 + t;
                if (r0 < NN) C2[base]      = make_float2(x0, x1);
                if (r1 < NN) C2[base + 32] = make_float2(x2, x3);
            } else {
                if (r0 < NN) *(float2*)(Cout + (size_t)r0 * HID + c0) = make_float2(v0, v1);
                if (r1 < NN) *(float2*)(Cout + (size_t)r1 * HID + c0) = make_float2(v2, v3);
            }
        }
    }
}

// ---------------- fp32 SIMT GEMM (head only) ----------------
template <int RELU>
__global__ void k_gemm(const float* __restrict__ A, const float* __restrict__ B,
                       const float* __restrict__ bias, float* __restrict__ C,
                       int M, int N, int K) {
    __shared__ float As[16][64];
    __shared__ float Bs[16][64];
    int tid = threadIdx.x;
    int tx = tid & 15, ty = tid >> 4;
    int bm = blockIdx.x * 64, bn = blockIdx.y * 64;
    int aR = tid >> 2;
    int aC = (tid & 3) * 4;
    int bR = tid >> 4;
    int bC = (tid & 15) * 4;
    int gArow = bm + aR;
    float acc[4][4] = {};
    for (int k0 = 0; k0 < K; k0 += 16) {
        float4 av = (gArow < M) ? *(const float4*)(A + (size_t)gArow * K + k0 + aC)
                                : make_float4(0.f, 0.f, 0.f, 0.f);
        As[aC + 0][aR] = av.x;
        As[aC + 1][aR] = av.y;
        As[aC + 2][aR] = av.z;
        As[aC + 3][aR] = av.w;
        *(float4*)&Bs[bR][bC] = *(const float4*)(B + (size_t)(k0 + bR) * N + bn + bC);
        __syncthreads();
        #pragma unroll
        for (int k = 0; k < 16; k++) {
            float4 a4 = *(const float4*)&As[k][ty * 4];
            float4 b4 = *(const float4*)&Bs[k][tx * 4];
            float ar[4] = {a4.x, a4.y, a4.z, a4.w};
            float br[4] = {b4.x, b4.y, b4.z, b4.w};
            #pragma unroll
            for (int i = 0; i < 4; i++)
                #pragma unroll
                for (int j = 0; j < 4; j++)
                    acc[i][j] += ar[i] * br[j];
        }
        __syncthreads();
    }
    #pragma unroll
    for (int i = 0; i < 4; i++) {
        int r = bm + ty * 4 + i;
        if (r < M) {
            #pragma unroll
            for (int j = 0; j < 4; j++) {
                int c = bn + tx * 4 + j;
                float v = acc[i][j] + bias[c];
                if (RELU) v = fmaxf(v, 0.f);
                C[(size_t)r * N + c] = v;
            }
        }
    }
}

// ---------------- batchnorm ----------------
__global__ void k_bn_reduce(const float* __restrict__ z) {
    int c = threadIdx.x;
    int r0 = blockIdx.x * 256;
    int r1 = min(r0 + 256, NN);
    float s = 0.f, s2 = 0.f;
    for (int r = r0; r < r1; r++) {
        float v = z[(size_t)r * HID + c];
        s += v; s2 += v * v;
    }
    atomicAdd(&g_bnsum[c], s);
    atomicAdd(&g_bnsum[HID + c], s2);
}

__global__ void k_bn_fin(const float* __restrict__ gamma, const float* __restrict__ beta) {
    int c = threadIdx.x;
    float mu = g_bnsum[c] * (1.f / NN);
    float var = g_bnsum[HID + c] * (1.f / NN) - mu * mu;
    float inv = rsqrtf(var + BN_EPS);
    float sc = inv * gamma[c];
    g_bnscale[c] = sc;
    g_bnshift[c] = beta[c] - mu * sc;
    g_bnsum[c] = 0.f;          // reset for next layer
    g_bnsum[HID + c] = 0.f;
}

__global__ void k_bn_apply() {
    int i = blockIdx.x * blockDim.x + threadIdx.x;
    if (i < NN * HID) {
        int c = i & (HID - 1);
        float v = g_z2[i] * g_bnscale[c] + g_bnshift[c];
        g_h[i] = fmaxf(v, 0.f) + g_h[i];
    }
}

// ---------------- pooling ----------------
__global__ void k_pool(const int* __restrict__ batch) {
    __shared__ int sb[128];
    int c = threadIdx.x;
    int n0 = blockIdx.x * 128;
    int n1 = min(n0 + 128, NN);
    if (c < 128 && n0 + c < NN) sb[c] = batch[n0 + c];
    __syncthreads();
    float accS = 0.f, accM = 0.f;
    int cur = sb[0];
    int cnt = 0;
    for (int n = n0; n < n1; n++) {
        int gg = sb[n - n0];
        if (gg != cur) {
            atomicAdd(&g_psum[cur * HID + c], accS);
            atomicMax((int*)&g_pmax[cur * HID + c], __float_as_int(accM));
            if (c == 0) atomicAdd(&g_cnt[cur], cnt);
            accS = 0.f; accM = 0.f; cnt = 0; cur = gg;
        }
        float v = g_h[(size_t)n * HID + c];
        accS += v;
        accM = fmaxf(accM, v);
        cnt++;
    }
    atomicAdd(&g_psum[cur * HID + c], accS);
    atomicMax((int*)&g_pmax[cur * HID + c], __float_as_int(accM));
    if (c == 0) atomicAdd(&g_cnt[cur], cnt);
}

__global__ void k_pool_fin() {
    int g = blockIdx.x, c = threadIdx.x;
    float s = g_psum[g * HID + c];
    float cnt = (float)max(g_cnt[g], 1);
    g_gfeat[g * 3 * HID + c]            = s / cnt;
    g_gfeat[g * 3 * HID + HID + c]      = s;
    g_gfeat[g * 3 * HID + 2 * HID + c]  = g_pmax[g * HID + c];
}

// ---------------- head final ----------------
__global__ void k_final(const float* __restrict__ W3, const float* __restrict__ b3,
                        float* __restrict__ out) {
    __shared__ float red[128];
    int g = blockIdx.x, t = threadIdx.x;
    red[t] = g_h2[g * 128 + t] * W3[t];
    __syncthreads();
    for (int off = 64; off > 0; off >>= 1) {
        if (t < off) red[t] += red[t + off];
        __syncthreads();
    }
    if (t == 0) out[g] = red[0] + b3[0];
}

// ---------------- launch ----------------
extern "C" void kernel_launch(void* const* d_in, const int* in_sizes, int n_in,
                              void* d_out, int out_size) {
    const float* x     = (const float*)d_in[0];
    const int*   ei    = (const int*)  d_in[1];
    const float* eattr = (const float*)d_in[2];
    const int*   batch = (const int*)  d_in[3];
    const float* encW  = (const float*)d_in[4];
    const float* encb  = (const float*)d_in[5];
    const float* edgeW = (const float*)d_in[6];
    const float* edgeb = (const float*)d_in[7];
    const float* W1    = (const float*)d_in[8];
    const float* b1    = (const float*)d_in[9];
    const float* W2    = (const float*)d_in[10];
    const float* b2    = (const float*)d_in[11];
    const float* bng   = (const float*)d_in[12];
    const float* bnb   = (const float*)d_in[13];
    const float* hW1   = (const float*)d_in[14];
    const float* hb1   = (const float*)d_in[15];
    const float* hW2   = (const float*)d_in[16];
    const float* hb2   = (const float*)d_in[17];
    const float* hW3   = (const float*)d_in[18];
    const float* hb3   = (const float*)d_in[19];
    float* out = (float*)d_out;

    float *p_z2, *p_gf, *p_h1, *p_h2, *p_a0f, *p_a1f, *p_wf;
    cudaGetSymbolAddress((void**)&p_z2, g_z2);
    cudaGetSymbolAddress((void**)&p_gf, g_gfeat);
    cudaGetSymbolAddress((void**)&p_h1, g_h1);
    cudaGetSymbolAddress((void**)&p_h2, g_h2);
    cudaGetSymbolAddress((void**)&p_a0f, g_a0f);
    cudaGetSymbolAddress((void**)&p_a1f, g_a1f);
    cudaGetSymbolAddress((void**)&p_wf, g_wf);

    cudaFuncSetAttribute(k_gemm_f<1>, cudaFuncAttributeMaxDynamicSharedMemorySize, GEMM_SMEM);
    cudaFuncSetAttribute(k_gemm_f<0>, cudaFuncAttributeMaxDynamicSharedMemorySize, GEMM_SMEM);

    // CSR build + init + weight prep
    k_zero_init<<<512, 256>>>();
    k_hist<<<(NE + 255) / 256, 256>>>(ei);
    k_scan<<<1, 1024>>>();
    k_scatter<<<(NE + 255) / 256, 256>>>(ei);
    k_wprep<<<8, 256>>>(W1, W2);

    // encoder
    k_enc<<<NN, HID>>>(x, encW, encb);

    dim3 gg(NNPAD / 128, 2);
    for (int l = 0; l < NL; l++) {
        k_aggregate<<<(NN + 7) / 8, 256>>>(eattr, edgeW + l * EDIM * HID, edgeb + l * HID, p_a0f);
        k_gemm_f<1><<<gg, 256, GEMM_SMEM>>>(p_a0f, p_wf + (size_t)(l * 2 + 0) * HID * HID,
                                            b1 + l * HID, p_a1f);
        k_gemm_f<0><<<gg, 256, GEMM_SMEM>>>(p_a1f, p_wf + (size_t)(l * 2 + 1) * HID * HID,
                                            b2 + l * HID, p_z2);
        k_bn_reduce<<<(NN + 255) / 256, 256>>>(p_z2);
        k_bn_fin<<<1, 256>>>(bng + l * HID, bnb + l * HID);
        k_bn_apply<<<(NN * HID + 255) / 256, 256>>>();
    }

    // pooling + head
    k_pool<<<(NN + 127) / 128, 256>>>(batch);
    k_pool_fin<<<NG, HID>>>();
    k_gemm<1><<<dim3(NG / 64, HID / 64), 256>>>(p_gf, hW1, hb1, p_h1, NG, HID, 3 * HID);
    k_gemm<1><<<dim3(NG / 64, (HID / 2) / 64), 256>>>(p_h1, hW2, hb2, p_h2, NG, HID / 2, HID);
    k_final<<<NG, 128>>>(hW3, hb3, out);
}

// round 5
// speedup vs baseline: 2.5770x; 1.2066x over previous
#include <cuda_runtime.h>
#include <cuda_fp16.h>
#include <math.h>
#include <stdint.h>

#define NN    50000
#define NNPAD 50048   // 391 * 128
#define NE    300000
#define NDIM  11
#define EDIM  5
#define HID   256
#define NG    1024
#define NL    4
#define BN_EPS 1e-5f

// ---------------- scratch (device globals: allocation-free) ----------------
__device__ float  g_h  [NN*HID];
__device__ __half g_hh [NN*HID];       // half mirror of h (gather source)
__device__ float  g_z2 [NN*HID];
__device__ __half g_a0f[NNPAD*HID];    // GEMM1 A, fp16 fragment order
__device__ __half g_a1f[NNPAD*HID];    // GEMM2 A, fp16 fragment order
__device__ __half g_wf [8*HID*HID];    // weights, fp16 fragment order
__device__ int    g_deg[NN];
__device__ int    g_offs[NN+1];
__device__ int    g_cursor[NN];
__device__ int    g_ssrc[NE];
__device__ int    g_seid[NE];
__device__ float  g_bnsum[2*HID];
__device__ float  g_bnscale[HID];
__device__ float  g_bnshift[HID];
__device__ float  g_psum[NG*HID];
__device__ float  g_pmax[NG*HID];
__device__ int    g_cnt[NG];
__device__ float  g_gfeat[NG*3*HID];
__device__ float  g_h1[NG*HID];
__device__ float  g_h2[NG*(HID/2)];

// ---------------- helpers ----------------
__device__ __forceinline__ unsigned pack2(float a, float b) {
    __half2 h = __floats2half2_rn(a, b);
    return *reinterpret_cast<unsigned*>(&h);
}
__device__ __forceinline__ float2 unpack2(unsigned u) {
    __half2 h = *reinterpret_cast<__half2*>(&u);
    return __half22float2(h);
}
__device__ __forceinline__ void cp16(void* s, const void* g) {
    unsigned sa = (unsigned)__cvta_generic_to_shared(s);
    asm volatile("cp.async.ca.shared.global [%0], [%1], 16;\n" :: "r"(sa), "l"(g));
}

// ---------------- init / CSR build ----------------
__global__ void k_zero_init() {
    int i = blockIdx.x * blockDim.x + threadIdx.x;
    int stride = gridDim.x * blockDim.x;
    for (int j = i; j < NN; j += stride) g_deg[j] = 0;
    for (int j = i; j < NG*HID; j += stride) { g_psum[j] = 0.f; g_pmax[j] = 0.f; }
    for (int j = i; j < NG; j += stride) g_cnt[j] = 0;
    for (int j = i; j < 2*HID; j += stride) g_bnsum[j] = 0.f;
}

__global__ void k_hist(const int* __restrict__ ei) {
    int e = blockIdx.x * blockDim.x + threadIdx.x;
    if (e < NE) atomicAdd(&g_deg[ei[NE + e]], 1);
}

__global__ void k_scan() {
    __shared__ int s[1024];
    const int CH = (NN + 1023) / 1024;
    int tid = threadIdx.x;
    int start = tid * CH;
    int sum = 0;
    for (int i = 0; i < CH; i++) {
        int idx = start + i;
        if (idx < NN) sum += g_deg[idx];
    }
    s[tid] = sum;
    __syncthreads();
    for (int off = 1; off < 1024; off <<= 1) {
        int v = 0;
        if (tid >= off) v = s[tid - off];
        __syncthreads();
        if (tid >= off) s[tid] += v;
        __syncthreads();
    }
    int run = (tid == 0) ? 0 : s[tid - 1];
    for (int i = 0; i < CH; i++) {
        int idx = start + i;
        if (idx < NN) {
            g_offs[idx] = run;
            g_cursor[idx] = run;
            run += g_deg[idx];
        }
    }
    if (tid == 1023) g_offs[NN] = s[1023];
}

__global__ void k_scatter(const int* __restrict__ ei) {
    int e = blockIdx.x * blockDim.x + threadIdx.x;
    if (e < NE) {
        int s = ei[e];
        int d = ei[NE + e];
        int pos = atomicAdd(&g_cursor[d], 1);
        g_ssrc[pos] = s;
        g_seid[pos] = e;
    }
}

// ---------------- weight prep: fp16 fragment order ----------------
// unit (uint2) at [(N8*16+S)*32 + g*4 + t] = halfs {W[S*16+2t][n], W[..+2t+1][n], W[..+2t+8][n], W[..+2t+9][n]}, n=N8*8+g
__global__ void k_wprep(const float* __restrict__ W1, const float* __restrict__ W2) {
    int mat = blockIdx.x;           // 0..7 = layer*2 + (0:W1, 1:W2)
    int l = mat >> 1;
    const float* W = (mat & 1) ? (W2 + l * HID * HID) : (W1 + l * HID * HID);
    uint2* F = (uint2*)(g_wf + (size_t)mat * HID * HID);
    int n = threadIdx.x;            // 256
    int N8 = n >> 3, g = n & 7;
    for (int S = 0; S < 16; S++) {
        #pragma unroll
        for (int t = 0; t < 4; t++) {
            int k0 = S * 16 + 2 * t;
            float w0 = W[(k0    ) * HID + n];
            float w1 = W[(k0 + 1) * HID + n];
            float w8 = W[(k0 + 8) * HID + n];
            float w9 = W[(k0 + 9) * HID + n];
            F[(N8 * 16 + S) * 32 + g * 4 + t] = make_uint2(pack2(w0, w1), pack2(w8, w9));
        }
    }
}

// ---------------- node encoder ----------------
__global__ void k_enc(const float* __restrict__ x, const float* __restrict__ W,
                      const float* __restrict__ b) {
    __shared__ float sx[NDIM];
    int node = blockIdx.x;
    int c = threadIdx.x;
    if (c < NDIM) sx[c] = x[node * NDIM + c];
    __syncthreads();
    float a = b[c];
    #pragma unroll
    for (int k = 0; k < NDIM; k++) a += sx[k] * W[k * HID + c];
    float v = fmaxf(a, 0.f);
    g_h [(size_t)node * HID + c] = v;
    g_hh[(size_t)node * HID + c] = __float2half(v);
}

// ---------------- GINE aggregation -> fp16 fragment-order A ----------------
// lane l: S = l>>1, t0 = l&1. Owns channels S*16 + {2t0,2t0+1, 2t0+8,2t0+9, 2t0+4,2t0+5, 2t0+12,2t0+13}
__global__ void k_aggregate(const float* __restrict__ edge_attr,
                            const float* __restrict__ eW,
                            const float* __restrict__ eb,
                            __half* __restrict__ Afrag) {
    __shared__ float sWt[EDIM * 256];   // [d][j*32 + l]
    for (int i = threadIdx.x; i < EDIM * 256; i += 256) {
        int d = i >> 8, c = i & 255;
        int S = c >> 4, k = c & 15;
        int t0 = (k >> 1) & 1, bb = k & 1, grp = k >> 2;
        int j = bb + ((grp & 1) << 2) + ((grp >> 1) << 1);
        int l = S * 2 + t0;
        sWt[d * 256 + j * 32 + l] = eW[i];
    }
    __syncthreads();
    int warp = threadIdx.x >> 5, l = threadIdx.x & 31;
    int node = blockIdx.x * 8 + warp;
    if (node >= NN) return;
    int S = l >> 1, t0 = l & 1;
    int base2 = S * 8 + t0;          // in 2-channel units

    float ebr[8];
    {
        const float2* eb2 = (const float2*)eb;
        float2 e0 = eb2[base2],     e1 = eb2[base2 + 4];
        float2 e2 = eb2[base2 + 2], e3 = eb2[base2 + 6];
        ebr[0]=e0.x; ebr[1]=e0.y; ebr[2]=e1.x; ebr[3]=e1.y;
        ebr[4]=e2.x; ebr[5]=e2.y; ebr[6]=e3.x; ebr[7]=e3.y;
    }
    float wj[8][EDIM];
    #pragma unroll
    for (int j = 0; j < 8; j++)
        #pragma unroll
        for (int d = 0; d < EDIM; d++) wj[j][d] = sWt[d * 256 + j * 32 + l];

    float acc[8] = {0,0,0,0,0,0,0,0};
    const unsigned* hh2 = (const unsigned*)g_hh;
    int e0i = g_offs[node], e1i = g_offs[node + 1];
    for (int e = e0i; e < e1i; e++) {
        int src = g_ssrc[e];
        int eid = g_seid[e];
        float ea0 = edge_attr[eid*EDIM+0];
        float ea1 = edge_attr[eid*EDIM+1];
        float ea2 = edge_attr[eid*EDIM+2];
        float ea3 = edge_attr[eid*EDIM+3];
        float ea4 = edge_attr[eid*EDIM+4];
        size_t rb = (size_t)src * 128 + base2;
        float2 h0 = unpack2(hh2[rb]);
        float2 h1 = unpack2(hh2[rb + 4]);
        float2 h2 = unpack2(hh2[rb + 2]);
        float2 h3 = unpack2(hh2[rb + 6]);
        float hr[8] = {h0.x,h0.y,h1.x,h1.y,h2.x,h2.y,h3.x,h3.y};
        #pragma unroll
        for (int j = 0; j < 8; j++) {
            float m = hr[j] + ebr[j]
                    + ea0 * wj[j][0] + ea1 * wj[j][1] + ea2 * wj[j][2]
                    + ea3 * wj[j][3] + ea4 * wj[j][4];
            acc[j] += fmaxf(m, 0.f);
        }
    }
    // residual h (fp32) at same channels
    const float2* h2p = (const float2*)g_h;
    size_t nb = (size_t)node * 128 + base2;
    float2 v0 = h2p[nb], v1 = h2p[nb + 4], v2 = h2p[nb + 2], v3 = h2p[nb + 6];
    float hv[8] = {v0.x,v0.y,v1.x,v1.y,v2.x,v2.y,v3.x,v3.y};
    float rv[8];
    #pragma unroll
    for (int j = 0; j < 8; j++) rv[j] = hv[j] + acc[j];

    int R = node >> 4, g = node & 7, h = (node >> 3) & 1;
    uint2* A2 = (uint2*)Afrag;
    size_t ubase = ((size_t)(R * 16 + S) * 2 + h) * 32;
    A2[ubase + g * 4 + t0]     = make_uint2(pack2(rv[0], rv[1]), pack2(rv[2], rv[3]));
    A2[ubase + g * 4 + t0 + 2] = make_uint2(pack2(rv[4], rv[5]), pack2(rv[6], rv[7]));
}

// ---------------- fp16 fragment-order tensor GEMM ----------------
// C[M,256] = A[M,256] @ W. Block 128x128, 8 warps (2x4), warp 64x32, m16n8k16.
// 4 stages of K=64, double-buffered cp.async. FRAG_OUT=1: relu+bias -> fp16 frag.
// FRAG_OUT=0: fp32 row-major + fused BN sum/sumsq atomics.
#define GEMM_SMEM 65536
template <int FRAG_OUT>
__global__ void __launch_bounds__(256, 2)
k_gemm_h(const __half* __restrict__ Af, const __half* __restrict__ Bf,
         const float* __restrict__ bias, float* __restrict__ Cf,
         __half* __restrict__ Cfrag) {
    extern __shared__ char sm[];
    const int tid = threadIdx.x;
    const int wid = tid >> 5, lane = tid & 31;
    const int g = lane >> 2, t = lane & 3;
    const int warpRow = wid >> 2;      // 0..1
    const int wc = wid & 3;            // 0..3
    const int bm = blockIdx.x * 128;
    const int bn = blockIdx.y * 128;
    const int Rbase  = bm >> 4;
    const int N8base = bn >> 3;

    float acc[4][4][4];
    #pragma unroll
    for (int i = 0; i < 4; i++)
        #pragma unroll
        for (int j = 0; j < 4; j++) {
            acc[i][j][0]=0.f; acc[i][j][1]=0.f; acc[i][j][2]=0.f; acc[i][j][3]=0.f;
        }

    auto load_stage = [&](int buf, int st) {
        char* sA = sm + buf * 32768;
        char* sB = sA + 16384;
        const int Sbase = st * 4;
        #pragma unroll
        for (int i = 0; i < 4; i++) {
            int ch = tid + i * 256;
            {   // A: 1024 x 16B. per R: 4 slices x 512B = 2KB contiguous
                int R = ch >> 7, rem = ch & 127;
                const char* gp = (const char*)Af +
                    (((size_t)(Rbase + R) * 16 + Sbase) * 512 + rem * 16);
                cp16(sA + ch * 16, gp);
            }
            {   // B: 1024 x 16B. per N8: 4 slices x 256B = 1KB contiguous
                int N8 = ch >> 6, rem = ch & 63;
                const char* gp = (const char*)Bf +
                    (((size_t)(N8base + N8) * 16 + Sbase) * 256 + rem * 16);
                cp16(sB + ch * 16, gp);
            }
        }
        asm volatile("cp.async.commit_group;");
    };

    load_stage(0, 0);
    const int NSTAGE = 4;
    for (int st = 0; st < NSTAGE; st++) {
        int buf = st & 1;
        if (st + 1 < NSTAGE) {
            load_stage(buf ^ 1, st + 1);
            asm volatile("cp.async.wait_group 1;");
        } else {
            asm volatile("cp.async.wait_group 0;");
        }
        __syncthreads();

        const uint2* sA2 = (const uint2*)(sm + buf * 32768);
        const uint2* sB2 = (const uint2*)(sm + buf * 32768 + 16384);
        #pragma unroll
        for (int Sl = 0; Sl < 4; Sl++) {
            unsigned af[4][4];
            unsigned bf[4][2];
            #pragma unroll
            for (int mt = 0; mt < 4; mt++) {
                int mtIdx = warpRow * 4 + mt;
                uint2 u0 = sA2[((mtIdx * 4 + Sl) * 2 + 0) * 32 + lane];
                uint2 u1 = sA2[((mtIdx * 4 + Sl) * 2 + 1) * 32 + lane];
                af[mt][0] = u0.x; af[mt][1] = u1.x; af[mt][2] = u0.y; af[mt][3] = u1.y;
            }
            #pragma unroll
            for (int nt = 0; nt < 4; nt++) {
                uint2 ub = sB2[((wc * 4 + nt) * 4 + Sl) * 32 + lane];
                bf[nt][0] = ub.x; bf[nt][1] = ub.y;
            }
            #pragma unroll
            for (int mt = 0; mt < 4; mt++)
                #pragma unroll
                for (int nt = 0; nt < 4; nt++) {
                    asm volatile(
                        "mma.sync.aligned.m16n8k16.row.col.f32.f16.f16.f32 "
                        "{%0,%1,%2,%3}, {%4,%5,%6,%7}, {%8,%9}, {%0,%1,%2,%3};\n"
                        : "+f"(acc[mt][nt][0]), "+f"(acc[mt][nt][1]),
                          "+f"(acc[mt][nt][2]), "+f"(acc[mt][nt][3])
                        : "r"(af[mt][0]), "r"(af[mt][1]), "r"(af[mt][2]), "r"(af[mt][3]),
                          "r"(bf[nt][0]), "r"(bf[nt][1]));
                }
        }
        __syncthreads();
    }

    const unsigned FULL = 0xffffffffu;
    if (FRAG_OUT) {
        // relu(acc+bias) -> fp16 fragment-order for next GEMM (no shuffles needed)
        uint2* C2 = (uint2*)Cfrag;
        #pragma unroll
        for (int mt = 0; mt < 4; mt++) {
            int r0 = bm + warpRow * 64 + mt * 16 + g;
            int r1 = r0 + 8;
            int R = r0 >> 4;
            #pragma unroll
            for (int j = 0; j < 2; j++) {
                int S = (bn >> 4) + wc * 2 + j;
                int ntA = 2 * j, ntB = 2 * j + 1;
                int cA = bn + wc * 32 + ntA * 8 + 2 * t;
                int cB = cA + 8;
                float bA0 = bias[cA], bA1 = bias[cA + 1];
                float bB0 = bias[cB], bB1 = bias[cB + 1];
                float a0 = fmaxf(acc[mt][ntA][0] + bA0, 0.f);
                float a1 = fmaxf(acc[mt][ntA][1] + bA1, 0.f);
                float a2 = fmaxf(acc[mt][ntA][2] + bA0, 0.f);
                float a3 = fmaxf(acc[mt][ntA][3] + bA1, 0.f);
                float b0 = fmaxf(acc[mt][ntB][0] + bB0, 0.f);
                float b1 = fmaxf(acc[mt][ntB][1] + bB1, 0.f);
                float b2 = fmaxf(acc[mt][ntB][2] + bB0, 0.f);
                float b3 = fmaxf(acc[mt][ntB][3] + bB1, 0.f);
                size_t ubase = ((size_t)(R * 16 + S) * 2) * 32;
                if (r0 < NN) C2[ubase + lane]      = make_uint2(pack2(a0, a1), pack2(b0, b1));
                if (r1 < NN) C2[ubase + 32 + lane] = make_uint2(pack2(a2, a3), pack2(b2, b3));
            }
        }
    } else {
        // fp32 row-major + fused BN column sums
        #pragma unroll
        for (int nt = 0; nt < 4; nt++) {
            int c0 = bn + wc * 32 + nt * 8 + 2 * t;
            float b0 = bias[c0], b1 = bias[c0 + 1];
            float s0 = 0.f, q0 = 0.f, s1 = 0.f, q1 = 0.f;
            #pragma unroll
            for (int mt = 0; mt < 4; mt++) {
                int r0 = bm + warpRow * 64 + mt * 16 + g;
                int r1 = r0 + 8;
                float v0 = acc[mt][nt][0] + b0;
                float v1 = acc[mt][nt][1] + b1;
                float v2 = acc[mt][nt][2] + b0;
                float v3 = acc[mt][nt][3] + b1;
                if (r0 < NN) {
                    *(float2*)(Cf + (size_t)r0 * HID + c0) = make_float2(v0, v1);
                    s0 += v0; q0 += v0 * v0; s1 += v1; q1 += v1 * v1;
                }
                if (r1 < NN) {
                    *(float2*)(Cf + (size_t)r1 * HID + c0) = make_float2(v2, v3);
                    s0 += v2; q0 += v2 * v2; s1 += v3; q1 += v3 * v3;
                }
            }
            #pragma unroll
            for (int off = 16; off >= 4; off >>= 1) {
                s0 += __shfl_down_sync(FULL, s0, off);
                q0 += __shfl_down_sync(FULL, q0, off);
                s1 += __shfl_down_sync(FULL, s1, off);
                q1 += __shfl_down_sync(FULL, q1, off);
            }
            if (lane < 4) {
                atomicAdd(&g_bnsum[c0],           s0);
                atomicAdd(&g_bnsum[c0 + 1],       s1);
                atomicAdd(&g_bnsum[HID + c0],     q0);
                atomicAdd(&g_bnsum[HID + c0 + 1], q1);
            }
        }
    }
}

// ---------------- fp32 SIMT GEMM (head only) ----------------
template <int RELU>
__global__ void k_gemm(const float* __restrict__ A, const float* __restrict__ B,
                       const float* __restrict__ bias, float* __restrict__ C,
                       int M, int N, int K) {
    __shared__ float As[16][64];
    __shared__ float Bs[16][64];
    int tid = threadIdx.x;
    int tx = tid & 15, ty = tid >> 4;
    int bm = blockIdx.x * 64, bn = blockIdx.y * 64;
    int aR = tid >> 2;
    int aC = (tid & 3) * 4;
    int bR = tid >> 4;
    int bC = (tid & 15) * 4;
    int gArow = bm + aR;
    float acc[4][4] = {};
    for (int k0 = 0; k0 < K; k0 += 16) {
        float4 av = (gArow < M) ? *(const float4*)(A + (size_t)gArow * K + k0 + aC)
                                : make_float4(0.f, 0.f, 0.f, 0.f);
        As[aC + 0][aR] = av.x;
        As[aC + 1][aR] = av.y;
        As[aC + 2][aR] = av.z;
        As[aC + 3][aR] = av.w;
        *(float4*)&Bs[bR][bC] = *(const float4*)(B + (size_t)(k0 + bR) * N + bn + bC);
        __syncthreads();
        #pragma unroll
        for (int k = 0; k < 16; k++) {
            float4 a4 = *(const float4*)&As[k][ty * 4];
            float4 b4 = *(const float4*)&Bs[k][tx * 4];
            float ar[4] = {a4.x, a4.y, a4.z, a4.w};
            float br[4] = {b4.x, b4.y, b4.z, b4.w};
            #pragma unroll
            for (int i = 0; i < 4; i++)
                #pragma unroll
                for (int j = 0; j < 4; j++)
                    acc[i][j] += ar[i] * br[j];
        }
        __syncthreads();
    }
    #pragma unroll
    for (int i = 0; i < 4; i++) {
        int r = bm + ty * 4 + i;
        if (r < M) {
            #pragma unroll
            for (int j = 0; j < 4; j++) {
                int c = bn + tx * 4 + j;
                float v = acc[i][j] + bias[c];
                if (RELU) v = fmaxf(v, 0.f);
                C[(size_t)r * N + c] = v;
            }
        }
    }
}

// ---------------- batchnorm ----------------
__global__ void k_bn_fin(const float* __restrict__ gamma, const float* __restrict__ beta) {
    int c = threadIdx.x;
    float mu = g_bnsum[c] * (1.f / NN);
    float var = g_bnsum[HID + c] * (1.f / NN) - mu * mu;
    float inv = rsqrtf(var + BN_EPS);
    float sc = inv * gamma[c];
    g_bnscale[c] = sc;
    g_bnshift[c] = beta[c] - mu * sc;
    g_bnsum[c] = 0.f;
    g_bnsum[HID + c] = 0.f;
}

__global__ void k_bn_apply() {
    int i = blockIdx.x * blockDim.x + threadIdx.x;
    if (i < NN * HID) {
        int c = i & (HID - 1);
        float v = g_z2[i] * g_bnscale[c] + g_bnshift[c];
        float hn = fmaxf(v, 0.f) + g_h[i];
        g_h[i] = hn;
        g_hh[i] = __float2half(hn);
    }
}

// ---------------- pooling ----------------
__global__ void k_pool(const int* __restrict__ batch) {
    __shared__ int sb[128];
    int c = threadIdx.x;
    int n0 = blockIdx.x * 128;
    int n1 = min(n0 + 128, NN);
    if (c < 128 && n0 + c < NN) sb[c] = batch[n0 + c];
    __syncthreads();
    float accS = 0.f, accM = 0.f;
    int cur = sb[0];
    int cnt = 0;
    for (int n = n0; n < n1; n++) {
        int gg = sb[n - n0];
        if (gg != cur) {
            atomicAdd(&g_psum[cur * HID + c], accS);
            atomicMax((int*)&g_pmax[cur * HID + c], __float_as_int(accM));
            if (c == 0) atomicAdd(&g_cnt[cur], cnt);
            accS = 0.f; accM = 0.f; cnt = 0; cur = gg;
        }
        float v = g_h[(size_t)n * HID + c];
        accS += v;
        accM = fmaxf(accM, v);
        cnt++;
    }
    atomicAdd(&g_psum[cur * HID + c], accS);
    atomicMax((int*)&g_pmax[cur * HID + c], __float_as_int(accM));
    if (c == 0) atomicAdd(&g_cnt[cur], cnt);
}

__global__ void k_pool_fin() {
    int g = blockIdx.x, c = threadIdx.x;
    float s = g_psum[g * HID + c];
    float cnt = (float)max(g_cnt[g], 1);
    g_gfeat[g * 3 * HID + c]            = s / cnt;
    g_gfeat[g * 3 * HID + HID + c]      = s;
    g_gfeat[g * 3 * HID + 2 * HID + c]  = g_pmax[g * HID + c];
}

// ---------------- head final ----------------
__global__ void k_final(const float* __restrict__ W3, const float* __restrict__ b3,
                        float* __restrict__ out) {
    __shared__ float red[128];
    int g = blockIdx.x, t = threadIdx.x;
    red[t] = g_h2[g * 128 + t] * W3[t];
    __syncthreads();
    for (int off = 64; off > 0; off >>= 1) {
        if (t < off) red[t] += red[t + off];
        __syncthreads();
    }
    if (t == 0) out[g] = red[0] + b3[0];
}

// ---------------- launch ----------------
extern "C" void kernel_launch(void* const* d_in, const int* in_sizes, int n_in,
                              void* d_out, int out_size) {
    const float* x     = (const float*)d_in[0];
    const int*   ei    = (const int*)  d_in[1];
    const float* eattr = (const float*)d_in[2];
    const int*   batch = (const int*)  d_in[3];
    const float* encW  = (const float*)d_in[4];
    const float* encb  = (const float*)d_in[5];
    const float* edgeW = (const float*)d_in[6];
    const float* edgeb = (const float*)d_in[7];
    const float* W1    = (const float*)d_in[8];
    const float* b1    = (const float*)d_in[9];
    const float* W2    = (const float*)d_in[10];
    const float* b2    = (const float*)d_in[11];
    const float* bng   = (const float*)d_in[12];
    const float* bnb   = (const float*)d_in[13];
    const float* hW1   = (const float*)d_in[14];
    const float* hb1   = (const float*)d_in[15];
    const float* hW2   = (const float*)d_in[16];
    const float* hb2   = (const float*)d_in[17];
    const float* hW3   = (const float*)d_in[18];
    const float* hb3   = (const float*)d_in[19];
    float* out = (float*)d_out;

    float *p_z2, *p_gf, *p_h1, *p_h2;
    __half *p_a0f, *p_a1f, *p_wf;
    cudaGetSymbolAddress((void**)&p_z2, g_z2);
    cudaGetSymbolAddress((void**)&p_gf, g_gfeat);
    cudaGetSymbolAddress((void**)&p_h1, g_h1);
    cudaGetSymbolAddress((void**)&p_h2, g_h2);
    cudaGetSymbolAddress((void**)&p_a0f, g_a0f);
    cudaGetSymbolAddress((void**)&p_a1f, g_a1f);
    cudaGetSymbolAddress((void**)&p_wf, g_wf);

    cudaFuncSetAttribute(k_gemm_h<1>, cudaFuncAttributeMaxDynamicSharedMemorySize, GEMM_SMEM);
    cudaFuncSetAttribute(k_gemm_h<0>, cudaFuncAttributeMaxDynamicSharedMemorySize, GEMM_SMEM);

    // CSR build + init + weight prep
    k_zero_init<<<512, 256>>>();
    k_hist<<<(NE + 255) / 256, 256>>>(ei);
    k_scan<<<1, 1024>>>();
    k_scatter<<<(NE + 255) / 256, 256>>>(ei);
    k_wprep<<<8, 256>>>(W1, W2);

    // encoder
    k_enc<<<NN, HID>>>(x, encW, encb);

    dim3 gg(NNPAD / 128, 2);
    for (int l = 0; l < NL; l++) {
        k_aggregate<<<(NN + 7) / 8, 256>>>(eattr, edgeW + l * EDIM * HID, edgeb + l * HID, p_a0f);
        k_gemm_h<1><<<gg, 256, GEMM_SMEM>>>(p_a0f, p_wf + (size_t)(l * 2 + 0) * HID * HID,
                                            b1 + l * HID, nullptr, p_a1f);
        k_gemm_h<0><<<gg, 256, GEMM_SMEM>>>(p_a1f, p_wf + (size_t)(l * 2 + 1) * HID * HID,
                                            b2 + l * HID, p_z2, nullptr);
        k_bn_fin<<<1, 256>>>(bng + l * HID, bnb + l * HID);
        k_bn_apply<<<(NN * HID + 255) / 256, 256>>>();
    }

    // pooling + head
    k_pool<<<(NN + 127) / 128, 256>>>(batch);
    k_pool_fin<<<NG, HID>>>();
    k_gemm<1><<<dim3(NG / 64, HID / 64), 256>>>(p_gf, hW1, hb1, p_h1, NG, HID, 3 * HID);
    k_gemm<1><<<dim3(NG / 64, (HID / 2) / 64), 256>>>(p_h1, hW2, hb2, p_h2, NG, HID / 2, HID);
    k_final<<<NG, 128>>>(hW3, hb3, out);
}

// round 6
// speedup vs baseline: 2.6850x; 1.0419x over previous
#include <cuda_runtime.h>
#include <cuda_fp16.h>
#include <math.h>
#include <stdint.h>

#define NN    50000
#define NNPAD 50048   // 391 * 128
#define NE    300000
#define NDIM  11
#define EDIM  5
#define HID   256
#define NG    1024
#define NL    4
#define BN_EPS 1e-5f

// ---------------- scratch (device globals: allocation-free) ----------------
__device__ float  g_h  [NN*HID];
__device__ __half g_hh [NN*HID];       // half mirror of h (gather source)
__device__ float  g_z2 [NN*HID];
__device__ __half g_a0f[NNPAD*HID];    // MLP input A, fp16 fragment order
__device__ __half g_wf [8*HID*HID];    // weights, fp16 fragment order
__device__ int    g_deg[NN];
__device__ int    g_offs[NN+1];
__device__ int    g_cursor[NN];
__device__ int    g_ssrc[NE];
__device__ int    g_seid[NE];
__device__ float  g_bnsum[2*HID];
__device__ float  g_bnscale[HID];
__device__ float  g_bnshift[HID];
__device__ float  g_psum[NG*HID];
__device__ float  g_pmax[NG*HID];
__device__ int    g_cnt[NG];
__device__ float  g_gfeat[NG*3*HID];
__device__ float  g_h1[NG*HID];
__device__ float  g_h2[NG*(HID/2)];

// ---------------- helpers ----------------
__device__ __forceinline__ unsigned pack2(float a, float b) {
    __half2 h = __floats2half2_rn(a, b);
    return *reinterpret_cast<unsigned*>(&h);
}
__device__ __forceinline__ float2 unpack2(unsigned u) {
    __half2 h = *reinterpret_cast<__half2*>(&u);
    return __half22float2(h);
}
__device__ __forceinline__ void cp16(void* s, const void* g) {
    unsigned sa = (unsigned)__cvta_generic_to_shared(s);
    asm volatile("cp.async.ca.shared.global [%0], [%1], 16;\n" :: "r"(sa), "l"(g));
}

// ---------------- init / CSR build ----------------
__global__ void k_zero_init() {
    int i = blockIdx.x * blockDim.x + threadIdx.x;
    int stride = gridDim.x * blockDim.x;
    for (int j = i; j < NN; j += stride) g_deg[j] = 0;
    for (int j = i; j < NG*HID; j += stride) { g_psum[j] = 0.f; g_pmax[j] = 0.f; }
    for (int j = i; j < NG; j += stride) g_cnt[j] = 0;
    for (int j = i; j < 2*HID; j += stride) g_bnsum[j] = 0.f;
}

__global__ void k_hist(const int* __restrict__ ei) {
    int e = blockIdx.x * blockDim.x + threadIdx.x;
    if (e < NE) atomicAdd(&g_deg[ei[NE + e]], 1);
}

__global__ void k_scan() {
    __shared__ int s[1024];
    const int CH = (NN + 1023) / 1024;
    int tid = threadIdx.x;
    int start = tid * CH;
    int sum = 0;
    for (int i = 0; i < CH; i++) {
        int idx = start + i;
        if (idx < NN) sum += g_deg[idx];
    }
    s[tid] = sum;
    __syncthreads();
    for (int off = 1; off < 1024; off <<= 1) {
        int v = 0;
        if (tid >= off) v = s[tid - off];
        __syncthreads();
        if (tid >= off) s[tid] += v;
        __syncthreads();
    }
    int run = (tid == 0) ? 0 : s[tid - 1];
    for (int i = 0; i < CH; i++) {
        int idx = start + i;
        if (idx < NN) {
            g_offs[idx] = run;
            g_cursor[idx] = run;
            run += g_deg[idx];
        }
    }
    if (tid == 1023) g_offs[NN] = s[1023];
}

__global__ void k_scatter(const int* __restrict__ ei) {
    int e = blockIdx.x * blockDim.x + threadIdx.x;
    if (e < NE) {
        int s = ei[e];
        int d = ei[NE + e];
        int pos = atomicAdd(&g_cursor[d], 1);
        g_ssrc[pos] = s;
        g_seid[pos] = e;
    }
}

// ---------------- weight prep: fp16 fragment order ----------------
__global__ void k_wprep(const float* __restrict__ W1, const float* __restrict__ W2) {
    int mat = blockIdx.x;           // 0..7 = layer*2 + (0:W1, 1:W2)
    int l = mat >> 1;
    const float* W = (mat & 1) ? (W2 + l * HID * HID) : (W1 + l * HID * HID);
    uint2* F = (uint2*)(g_wf + (size_t)mat * HID * HID);
    int n = threadIdx.x;            // 256
    int N8 = n >> 3, g = n & 7;
    for (int S = 0; S < 16; S++) {
        #pragma unroll
        for (int t = 0; t < 4; t++) {
            int k0 = S * 16 + 2 * t;
            float w0 = W[(k0    ) * HID + n];
            float w1 = W[(k0 + 1) * HID + n];
            float w8 = W[(k0 + 8) * HID + n];
            float w9 = W[(k0 + 9) * HID + n];
            F[(N8 * 16 + S) * 32 + g * 4 + t] = make_uint2(pack2(w0, w1), pack2(w8, w9));
        }
    }
}

// ---------------- node encoder ----------------
__global__ void k_enc(const float* __restrict__ x, const float* __restrict__ W,
                      const float* __restrict__ b) {
    __shared__ float sx[NDIM];
    int node = blockIdx.x;
    int c = threadIdx.x;
    if (c < NDIM) sx[c] = x[node * NDIM + c];
    __syncthreads();
    float a = b[c];
    #pragma unroll
    for (int k = 0; k < NDIM; k++) a += sx[k] * W[k * HID + c];
    float v = fmaxf(a, 0.f);
    g_h [(size_t)node * HID + c] = v;
    g_hh[(size_t)node * HID + c] = __float2half(v);
}

// ---------------- GINE aggregation -> fp16 fragment-order A ----------------
__global__ void k_aggregate(const float* __restrict__ edge_attr,
                            const float* __restrict__ eW,
                            const float* __restrict__ eb,
                            __half* __restrict__ Afrag) {
    __shared__ float sWt[EDIM * 256];   // [d][j*32 + l]
    for (int i = threadIdx.x; i < EDIM * 256; i += 256) {
        int d = i >> 8, c = i & 255;
        int S = c >> 4, k = c & 15;
        int t0 = (k >> 1) & 1, bb = k & 1, grp = k >> 2;
        int j = bb + ((grp & 1) << 2) + ((grp >> 1) << 1);
        int l = S * 2 + t0;
        sWt[d * 256 + j * 32 + l] = eW[i];
    }
    __syncthreads();
    int warp = threadIdx.x >> 5, l = threadIdx.x & 31;
    int node = blockIdx.x * 8 + warp;
    if (node >= NN) return;
    int S = l >> 1, t0 = l & 1;
    int base2 = S * 8 + t0;          // in 2-channel units

    float ebr[8];
    {
        const float2* eb2 = (const float2*)eb;
        float2 e0 = eb2[base2],     e1 = eb2[base2 + 4];
        float2 e2 = eb2[base2 + 2], e3 = eb2[base2 + 6];
        ebr[0]=e0.x; ebr[1]=e0.y; ebr[2]=e1.x; ebr[3]=e1.y;
        ebr[4]=e2.x; ebr[5]=e2.y; ebr[6]=e3.x; ebr[7]=e3.y;
    }
    float wj[8][EDIM];
    #pragma unroll
    for (int j = 0; j < 8; j++)
        #pragma unroll
        for (int d = 0; d < EDIM; d++) wj[j][d] = sWt[d * 256 + j * 32 + l];

    float acc[8] = {0,0,0,0,0,0,0,0};
    const unsigned* hh2 = (const unsigned*)g_hh;
    int e0i = g_offs[node], e1i = g_offs[node + 1];
    for (int e = e0i; e < e1i; e++) {
        int src = g_ssrc[e];
        int eid = g_seid[e];
        float ea0 = edge_attr[eid*EDIM+0];
        float ea1 = edge_attr[eid*EDIM+1];
        float ea2 = edge_attr[eid*EDIM+2];
        float ea3 = edge_attr[eid*EDIM+3];
        float ea4 = edge_attr[eid*EDIM+4];
        size_t rb = (size_t)src * 128 + base2;
        float2 h0 = unpack2(hh2[rb]);
        float2 h1 = unpack2(hh2[rb + 4]);
        float2 h2 = unpack2(hh2[rb + 2]);
        float2 h3 = unpack2(hh2[rb + 6]);
        float hr[8] = {h0.x,h0.y,h1.x,h1.y,h2.x,h2.y,h3.x,h3.y};
        #pragma unroll
        for (int j = 0; j < 8; j++) {
            float m = hr[j] + ebr[j]
                    + ea0 * wj[j][0] + ea1 * wj[j][1] + ea2 * wj[j][2]
                    + ea3 * wj[j][3] + ea4 * wj[j][4];
            acc[j] += fmaxf(m, 0.f);
        }
    }
    const float2* h2p = (const float2*)g_h;
    size_t nb = (size_t)node * 128 + base2;
    float2 v0 = h2p[nb], v1 = h2p[nb + 4], v2 = h2p[nb + 2], v3 = h2p[nb + 6];
    float hv[8] = {v0.x,v0.y,v1.x,v1.y,v2.x,v2.y,v3.x,v3.y};
    float rv[8];
    #pragma unroll
    for (int j = 0; j < 8; j++) rv[j] = hv[j] + acc[j];

    int R = node >> 4, g = node & 7, h = (node >> 3) & 1;
    uint2* A2 = (uint2*)Afrag;
    size_t ubase = ((size_t)(R * 16 + S) * 2 + h) * 32;
    A2[ubase + g * 4 + t0]     = make_uint2(pack2(rv[0], rv[1]), pack2(rv[2], rv[3]));
    A2[ubase + g * 4 + t0 + 2] = make_uint2(pack2(rv[4], rv[5]), pack2(rv[6], rv[7]));
}

// ---------------- fused MLP: z2 = (relu(A@W1+b1))@W2 + b2, + BN stats ------
// Block: 128 rows x full 256 cols. 8 warps (2x4), warp tile 64x64, m16n8k16.
// Phase 1 -> z1 in smem (fp16 frag order). Phase 2 -> fp32 z2 + BN atomics.
// smem: [0,32K) A stages (2x16K), [32K,96K) B stages (2x32K), [96K,160K) z1.
#define MLP_SMEM 163840
__global__ void __launch_bounds__(256, 1)
k_mlp(const __half* __restrict__ Af, const __half* __restrict__ W1f,
      const __half* __restrict__ W2f, const float* __restrict__ b1,
      const float* __restrict__ b2, float* __restrict__ Cf) {
    extern __shared__ char sm[];
    char* smA = sm;            // 2 x 16KB
    char* smB = sm + 32768;    // 2 x 32KB
    uint2* smZ = (uint2*)(sm + 98304);  // 64KB: [(Rl*16+S)*2+h]*32+lane

    const int tid = threadIdx.x;
    const int wid = tid >> 5, lane = tid & 31;
    const int g = lane >> 2, t = lane & 3;
    const int warpRow = wid >> 2;      // 0..1 (64 rows)
    const int wc = wid & 3;            // 0..3 (64 cols)
    const int bm = blockIdx.x * 128;
    const int Rbase = bm >> 4;
    const unsigned FULL = 0xffffffffu;

    float acc[4][8][4];

    auto load_A = [&](int buf, int st) {
        char* sA = smA + buf * 16384;
        const int Sbase = st * 4;
        #pragma unroll
        for (int i = 0; i < 4; i++) {
            int ch = tid + i * 256;          // 1024 chunks of 16B
            int R = ch >> 7, rem = ch & 127; // per R: 4 S-slices = 2KB contiguous
            const char* gp = (const char*)Af +
                (((size_t)(Rbase + R) * 16 + Sbase) * 512 + rem * 16);
            cp16(sA + ch * 16, gp);
        }
    };
    auto load_B = [&](int buf, int st, const __half* Bf) {
        char* sB = smB + buf * 32768;
        const int Sbase = st * 4;
        #pragma unroll
        for (int i = 0; i < 8; i++) {
            int ch = tid + i * 256;          // 2048 chunks of 16B
            int N8 = ch >> 6, rem = ch & 63; // per N8: 4 S-slices = 1KB contiguous
            const char* gp = (const char*)Bf +
                (((size_t)N8 * 16 + Sbase) * 256 + rem * 16);
            cp16(sB + ch * 16, gp);
        }
    };

    // ================= phase 1: z1 = relu(A@W1 + b1) =================
    #pragma unroll
    for (int i = 0; i < 4; i++)
        #pragma unroll
        for (int j = 0; j < 8; j++) {
            acc[i][j][0]=0.f; acc[i][j][1]=0.f; acc[i][j][2]=0.f; acc[i][j][3]=0.f;
        }

    load_A(0, 0); load_B(0, 0, W1f);
    asm volatile("cp.async.commit_group;");
    for (int st = 0; st < 4; st++) {
        int buf = st & 1;
        if (st + 1 < 4) {
            load_A(buf ^ 1, st + 1); load_B(buf ^ 1, st + 1, W1f);
            asm volatile("cp.async.commit_group;");
            asm volatile("cp.async.wait_group 1;");
        } else {
            asm volatile("cp.async.wait_group 0;");
        }
        __syncthreads();
        const uint2* sA2 = (const uint2*)(smA + buf * 16384);
        const uint2* sB2 = (const uint2*)(smB + buf * 32768);
        #pragma unroll
        for (int Sl = 0; Sl < 4; Sl++) {
            unsigned af[4][4];
            unsigned bf[8][2];
            #pragma unroll
            for (int mt = 0; mt < 4; mt++) {
                int mtIdx = warpRow * 4 + mt;
                uint2 u0 = sA2[((mtIdx * 4 + Sl) * 2 + 0) * 32 + lane];
                uint2 u1 = sA2[((mtIdx * 4 + Sl) * 2 + 1) * 32 + lane];
                af[mt][0] = u0.x; af[mt][1] = u1.x; af[mt][2] = u0.y; af[mt][3] = u1.y;
            }
            #pragma unroll
            for (int nt = 0; nt < 8; nt++) {
                uint2 ub = sB2[((wc * 8 + nt) * 4 + Sl) * 32 + lane];
                bf[nt][0] = ub.x; bf[nt][1] = ub.y;
            }
            #pragma unroll
            for (int mt = 0; mt < 4; mt++)
                #pragma unroll
                for (int nt = 0; nt < 8; nt++) {
                    asm volatile(
                        "mma.sync.aligned.m16n8k16.row.col.f32.f16.f16.f32 "
                        "{%0,%1,%2,%3}, {%4,%5,%6,%7}, {%8,%9}, {%0,%1,%2,%3};\n"
                        : "+f"(acc[mt][nt][0]), "+f"(acc[mt][nt][1]),
                          "+f"(acc[mt][nt][2]), "+f"(acc[mt][nt][3])
                        : "r"(af[mt][0]), "r"(af[mt][1]), "r"(af[mt][2]), "r"(af[mt][3]),
                          "r"(bf[nt][0]), "r"(bf[nt][1]));
                }
        }
        __syncthreads();
    }

    // prefetch W2 stage 0 into B buf0 (safe: buf0 reads finished at st=2 sync)
    load_B(0, 0, W2f);
    asm volatile("cp.async.commit_group;");

    // phase-1 epilogue: relu + b1 -> z1 smem fp16 frags
    #pragma unroll
    for (int mt = 0; mt < 4; mt++) {
        int rl0 = warpRow * 64 + mt * 16 + g;   // local row
        int Rl = rl0 >> 4;
        #pragma unroll
        for (int j = 0; j < 4; j++) {
            int S = wc * 4 + j;
            int ntA = 2 * j, ntB = 2 * j + 1;
            int cA = wc * 64 + ntA * 8 + 2 * t;
            int cB = cA + 8;
            float bA0 = b1[cA], bA1 = b1[cA + 1];
            float bB0 = b1[cB], bB1 = b1[cB + 1];
            float a0 = fmaxf(acc[mt][ntA][0] + bA0, 0.f);
            float a1 = fmaxf(acc[mt][ntA][1] + bA1, 0.f);
            float a2 = fmaxf(acc[mt][ntA][2] + bA0, 0.f);
            float a3 = fmaxf(acc[mt][ntA][3] + bA1, 0.f);
            float b0v = fmaxf(acc[mt][ntB][0] + bB0, 0.f);
            float b1v = fmaxf(acc[mt][ntB][1] + bB1, 0.f);
            float b2v = fmaxf(acc[mt][ntB][2] + bB0, 0.f);
            float b3v = fmaxf(acc[mt][ntB][3] + bB1, 0.f);
            int ubase = ((Rl * 16 + S) * 2) * 32;
            smZ[ubase + lane]      = make_uint2(pack2(a0, a1), pack2(b0v, b1v));
            smZ[ubase + 32 + lane] = make_uint2(pack2(a2, a3), pack2(b2v, b3v));
        }
    }

    // ================= phase 2: z2 = z1 @ W2 + b2 =================
    #pragma unroll
    for (int i = 0; i < 4; i++)
        #pragma unroll
        for (int j = 0; j < 8; j++) {
            acc[i][j][0]=0.f; acc[i][j][1]=0.f; acc[i][j][2]=0.f; acc[i][j][3]=0.f;
        }
    __syncthreads();   // z1 writes + W2 stage0 ordering

    for (int st = 0; st < 4; st++) {
        int buf = st & 1;
        if (st + 1 < 4) {
            load_B(buf ^ 1, st + 1, W2f);
            asm volatile("cp.async.commit_group;");
            asm volatile("cp.async.wait_group 1;");
        } else {
            asm volatile("cp.async.wait_group 0;");
        }
        __syncthreads();
        const uint2* sB2 = (const uint2*)(smB + buf * 32768);
        #pragma unroll
        for (int Sl = 0; Sl < 4; Sl++) {
            int S = st * 4 + Sl;
            unsigned af[4][4];
            unsigned bf[8][2];
            #pragma unroll
            for (int mt = 0; mt < 4; mt++) {
                int mtIdx = warpRow * 4 + mt;
                uint2 u0 = smZ[((mtIdx * 16 + S) * 2 + 0) * 32 + lane];
                uint2 u1 = smZ[((mtIdx * 16 + S) * 2 + 1) * 32 + lane];
                af[mt][0] = u0.x; af[mt][1] = u1.x; af[mt][2] = u0.y; af[mt][3] = u1.y;
            }
            #pragma unroll
            for (int nt = 0; nt < 8; nt++) {
                uint2 ub = sB2[((wc * 8 + nt) * 4 + Sl) * 32 + lane];
                bf[nt][0] = ub.x; bf[nt][1] = ub.y;
            }
            #pragma unroll
            for (int mt = 0; mt < 4; mt++)
                #pragma unroll
                for (int nt = 0; nt < 8; nt++) {
                    asm volatile(
                        "mma.sync.aligned.m16n8k16.row.col.f32.f16.f16.f32 "
                        "{%0,%1,%2,%3}, {%4,%5,%6,%7}, {%8,%9}, {%0,%1,%2,%3};\n"
                        : "+f"(acc[mt][nt][0]), "+f"(acc[mt][nt][1]),
                          "+f"(acc[mt][nt][2]), "+f"(acc[mt][nt][3])
                        : "r"(af[mt][0]), "r"(af[mt][1]), "r"(af[mt][2]), "r"(af[mt][3]),
                          "r"(bf[nt][0]), "r"(bf[nt][1]));
                }
        }
        __syncthreads();
    }

    // phase-2 epilogue: fp32 z2 + fused BN sums
    #pragma unroll
    for (int nt = 0; nt < 8; nt++) {
        int c0 = wc * 64 + nt * 8 + 2 * t;
        float b0 = b2[c0], b1v = b2[c0 + 1];
        float s0 = 0.f, q0 = 0.f, s1 = 0.f, q1 = 0.f;
        #pragma unroll
        for (int mt = 0; mt < 4; mt++) {
            int r0 = bm + warpRow * 64 + mt * 16 + g;
            int r1 = r0 + 8;
            float v0 = acc[mt][nt][0] + b0;
            float v1 = acc[mt][nt][1] + b1v;
            float v2 = acc[mt][nt][2] + b0;
            float v3 = acc[mt][nt][3] + b1v;
            if (r0 < NN) {
                *(float2*)(Cf + (size_t)r0 * HID + c0) = make_float2(v0, v1);
                s0 += v0; q0 += v0 * v0; s1 += v1; q1 += v1 * v1;
            }
            if (r1 < NN) {
                *(float2*)(Cf + (size_t)r1 * HID + c0) = make_float2(v2, v3);
                s0 += v2; q0 += v2 * v2; s1 += v3; q1 += v3 * v3;
            }
        }
        #pragma unroll
        for (int off = 16; off >= 4; off >>= 1) {
            s0 += __shfl_down_sync(FULL, s0, off);
            q0 += __shfl_down_sync(FULL, q0, off);
            s1 += __shfl_down_sync(FULL, s1, off);
            q1 += __shfl_down_sync(FULL, q1, off);
        }
        if (lane < 4) {
            atomicAdd(&g_bnsum[c0],           s0);
            atomicAdd(&g_bnsum[c0 + 1],       s1);
            atomicAdd(&g_bnsum[HID + c0],     q0);
            atomicAdd(&g_bnsum[HID + c0 + 1], q1);
        }
    }
}

// ---------------- fp32 SIMT GEMM (head only) ----------------
template <int RELU>
__global__ void k_gemm(const float* __restrict__ A, const float* __restrict__ B,
                       const float* __restrict__ bias, float* __restrict__ C,
                       int M, int N, int K) {
    __shared__ float As[16][64];
    __shared__ float Bs[16][64];
    int tid = threadIdx.x;
    int tx = tid & 15, ty = tid >> 4;
    int bm = blockIdx.x * 64, bn = blockIdx.y * 64;
    int aR = tid >> 2;
    int aC = (tid & 3) * 4;
    int bR = tid >> 4;
    int bC = (tid & 15) * 4;
    int gArow = bm + aR;
    float acc[4][4] = {};
    for (int k0 = 0; k0 < K; k0 += 16) {
        float4 av = (gArow < M) ? *(const float4*)(A + (size_t)gArow * K + k0 + aC)
                                : make_float4(0.f, 0.f, 0.f, 0.f);
        As[aC + 0][aR] = av.x;
        As[aC + 1][aR] = av.y;
        As[aC + 2][aR] = av.z;
        As[aC + 3][aR] = av.w;
        *(float4*)&Bs[bR][bC] = *(const float4*)(B + (size_t)(k0 + bR) * N + bn + bC);
        __syncthreads();
        #pragma unroll
        for (int k = 0; k < 16; k++) {
            float4 a4 = *(const float4*)&As[k][ty * 4];
            float4 b4 = *(const float4*)&Bs[k][tx * 4];
            float ar[4] = {a4.x, a4.y, a4.z, a4.w};
            float br[4] = {b4.x, b4.y, b4.z, b4.w};
            #pragma unroll
            for (int i = 0; i < 4; i++)
                #pragma unroll
                for (int j = 0; j < 4; j++)
                    acc[i][j] += ar[i] * br[j];
        }
        __syncthreads();
    }
    #pragma unroll
    for (int i = 0; i < 4; i++) {
        int r = bm + ty * 4 + i;
        if (r < M) {
            #pragma unroll
            for (int j = 0; j < 4; j++) {
                int c = bn + tx * 4 + j;
                float v = acc[i][j] + bias[c];
                if (RELU) v = fmaxf(v, 0.f);
                C[(size_t)r * N + c] = v;
            }
        }
    }
}

// ---------------- batchnorm ----------------
__global__ void k_bn_fin(const float* __restrict__ gamma, const float* __restrict__ beta) {
    int c = threadIdx.x;
    float mu = g_bnsum[c] * (1.f / NN);
    float var = g_bnsum[HID + c] * (1.f / NN) - mu * mu;
    float inv = rsqrtf(var + BN_EPS);
    float sc = inv * gamma[c];
    g_bnscale[c] = sc;
    g_bnshift[c] = beta[c] - mu * sc;
    g_bnsum[c] = 0.f;
    g_bnsum[HID + c] = 0.f;
}

__global__ void k_bn_apply() {
    int idx = blockIdx.x * blockDim.x + threadIdx.x;   // float4 index
    if (idx < NN * 64) {
        int c4 = idx & 63;
        float4 z = ((const float4*)g_z2)[idx];
        float4 sc = ((const float4*)g_bnscale)[c4];
        float4 sh = ((const float4*)g_bnshift)[c4];
        float4 hv = ((const float4*)g_h)[idx];
        float4 r;
        r.x = fmaxf(z.x * sc.x + sh.x, 0.f) + hv.x;
        r.y = fmaxf(z.y * sc.y + sh.y, 0.f) + hv.y;
        r.z = fmaxf(z.z * sc.z + sh.z, 0.f) + hv.z;
        r.w = fmaxf(z.w * sc.w + sh.w, 0.f) + hv.w;
        ((float4*)g_h)[idx] = r;
        uint2 u = make_uint2(pack2(r.x, r.y), pack2(r.z, r.w));
        ((uint2*)g_hh)[idx] = u;
    }
}

// ---------------- pooling ----------------
__global__ void k_pool(const int* __restrict__ batch) {
    __shared__ int sb[128];
    int c = threadIdx.x;
    int n0 = blockIdx.x * 128;
    int n1 = min(n0 + 128, NN);
    if (c < 128 && n0 + c < NN) sb[c] = batch[n0 + c];
    __syncthreads();
    float accS = 0.f, accM = 0.f;
    int cur = sb[0];
    int cnt = 0;
    for (int n = n0; n < n1; n++) {
        int gg = sb[n - n0];
        if (gg != cur) {
            atomicAdd(&g_psum[cur * HID + c], accS);
            atomicMax((int*)&g_pmax[cur * HID + c], __float_as_int(accM));
            if (c == 0) atomicAdd(&g_cnt[cur], cnt);
            accS = 0.f; accM = 0.f; cnt = 0; cur = gg;
        }
        float v = g_h[(size_t)n * HID + c];
        accS += v;
        accM = fmaxf(accM, v);
        cnt++;
    }
    atomicAdd(&g_psum[cur * HID + c], accS);
    atomicMax((int*)&g_pmax[cur * HID + c], __float_as_int(accM));
    if (c == 0) atomicAdd(&g_cnt[cur], cnt);
}

__global__ void k_pool_fin() {
    int g = blockIdx.x, c = threadIdx.x;
    float s = g_psum[g * HID + c];
    float cnt = (float)max(g_cnt[g], 1);
    g_gfeat[g * 3 * HID + c]            = s / cnt;
    g_gfeat[g * 3 * HID + HID + c]      = s;
    g_gfeat[g * 3 * HID + 2 * HID + c]  = g_pmax[g * HID + c];
}

// ---------------- head final ----------------
__global__ void k_final(const float* __restrict__ W3, const float* __restrict__ b3,
                        float* __restrict__ out) {
    __shared__ float red[128];
    int g = blockIdx.x, t = threadIdx.x;
    red[t] = g_h2[g * 128 + t] * W3[t];
    __syncthreads();
    for (int off = 64; off > 0; off >>= 1) {
        if (t < off) red[t] += red[t + off];
        __syncthreads();
    }
    if (t == 0) out[g] = red[0] + b3[0];
}

// ---------------- launch ----------------
extern "C" void kernel_launch(void* const* d_in, const int* in_sizes, int n_in,
                              void* d_out, int out_size) {
    const float* x     = (const float*)d_in[0];
    const int*   ei    = (const int*)  d_in[1];
    const float* eattr = (const float*)d_in[2];
    const int*   batch = (const int*)  d_in[3];
    const float* encW  = (const float*)d_in[4];
    const float* encb  = (const float*)d_in[5];
    const float* edgeW = (const float*)d_in[6];
    const float* edgeb = (const float*)d_in[7];
    const float* W1    = (const float*)d_in[8];
    const float* b1    = (const float*)d_in[9];
    const float* W2    = (const float*)d_in[10];
    const float* b2    = (const float*)d_in[11];
    const float* bng   = (const float*)d_in[12];
    const float* bnb   = (const float*)d_in[13];
    const float* hW1   = (const float*)d_in[14];
    const float* hb1   = (const float*)d_in[15];
    const float* hW2   = (const float*)d_in[16];
    const float* hb2   = (const float*)d_in[17];
    const float* hW3   = (const float*)d_in[18];
    const float* hb3   = (const float*)d_in[19];
    float* out = (float*)d_out;

    float *p_z2, *p_gf, *p_h1, *p_h2;
    __half *p_a0f, *p_wf;
    cudaGetSymbolAddress((void**)&p_z2, g_z2);
    cudaGetSymbolAddress((void**)&p_gf, g_gfeat);
    cudaGetSymbolAddress((void**)&p_h1, g_h1);
    cudaGetSymbolAddress((void**)&p_h2, g_h2);
    cudaGetSymbolAddress((void**)&p_a0f, g_a0f);
    cudaGetSymbolAddress((void**)&p_wf, g_wf);

    cudaFuncSetAttribute(k_mlp, cudaFuncAttributeMaxDynamicSharedMemorySize, MLP_SMEM);

    // CSR build + init + weight prep
    k_zero_init<<<512, 256>>>();
    k_hist<<<(NE + 255) / 256, 256>>>(ei);
    k_scan<<<1, 1024>>>();
    k_scatter<<<(NE + 255) / 256, 256>>>(ei);
    k_wprep<<<8, 256>>>(W1, W2);

    // encoder
    k_enc<<<NN, HID>>>(x, encW, encb);

    for (int l = 0; l < NL; l++) {
        k_aggregate<<<(NN + 7) / 8, 256>>>(eattr, edgeW + l * EDIM * HID, edgeb + l * HID, p_a0f);
        k_mlp<<<NNPAD / 128, 256, MLP_SMEM>>>(
            p_a0f,
            p_wf + (size_t)(l * 2 + 0) * HID * HID,
            p_wf + (size_t)(l * 2 + 1) * HID * HID,
            b1 + l * HID, b2 + l * HID, p_z2);
        k_bn_fin<<<1, 256>>>(bng + l * HID, bnb + l * HID);
        k_bn_apply<<<(NN * 64 + 511) / 512, 512>>>();
    }

    // pooling + head
    k_pool<<<(NN + 127) / 128, 256>>>(batch);
    k_pool_fin<<<NG, HID>>>();
    k_gemm<1><<<dim3(NG / 64, HID / 64), 256>>>(p_gf, hW1, hb1, p_h1, NG, HID, 3 * HID);
    k_gemm<1><<<dim3(NG / 64, (HID / 2) / 64), 256>>>(p_h1, hW2, hb2, p_h2, NG, HID / 2, HID);
    k_final<<<NG, 128>>>(hW3, hb3, out);
}

// round 7
// speedup vs baseline: 2.8460x; 1.0599x over previous
#include <cuda_runtime.h>
#include <cuda_fp16.h>
#include <math.h>
#include <stdint.h>

#define NN    50000
#define NNPAD 50048   // 391 * 128
#define NE    300000
#define NDIM  11
#define EDIM  5
#define HID   256
#define NG    1024
#define NL    4
#define BN_EPS 1e-5f

// ---------------- scratch (device globals: allocation-free) ----------------
__device__ float  g_h  [NN*HID];
__device__ __half g_hh [NN*HID];       // half mirror of h (gather source)
__device__ __half g_z2h[NN*HID];       // pre-BN MLP output (fp16)
__device__ __half g_a0f[NNPAD*HID];    // MLP input A, fp16 fragment order
__device__ __half g_wf [8*HID*HID];    // weights, fp16 fragment order
__device__ int    g_deg[NN];
__device__ int    g_offs[NN+1];
__device__ int    g_cursor[NN];
__device__ int    g_ssrc[NE];
__device__ int    g_seid[NE];
__device__ float  g_bnsum[2*HID];
__device__ float  g_bnscale[HID];
__device__ float  g_bnshift[HID];
__device__ float  g_psum[NG*HID];
__device__ float  g_pmax[NG*HID];
__device__ int    g_cnt[NG];
__device__ float  g_gfeat[NG*3*HID];
__device__ float  g_h1[NG*HID];
__device__ float  g_h2[NG*(HID/2)];

// ---------------- helpers ----------------
__device__ __forceinline__ unsigned pack2(float a, float b) {
    __half2 h = __floats2half2_rn(a, b);
    return *reinterpret_cast<unsigned*>(&h);
}
__device__ __forceinline__ float2 unpack2(unsigned u) {
    __half2 h = *reinterpret_cast<__half2*>(&u);
    return __half22float2(h);
}
__device__ __forceinline__ void cp16(void* s, const void* g) {
    unsigned sa = (unsigned)__cvta_generic_to_shared(s);
    asm volatile("cp.async.ca.shared.global [%0], [%1], 16;\n" :: "r"(sa), "l"(g));
}

// ---------------- init / CSR build ----------------
__global__ void k_zero_init() {
    int i = blockIdx.x * blockDim.x + threadIdx.x;
    int stride = gridDim.x * blockDim.x;
    for (int j = i; j < NN; j += stride) g_deg[j] = 0;
    for (int j = i; j < NG*HID; j += stride) { g_psum[j] = 0.f; g_pmax[j] = 0.f; }
    for (int j = i; j < NG; j += stride) g_cnt[j] = 0;
    for (int j = i; j < 2*HID; j += stride) g_bnsum[j] = 0.f;
}

__global__ void k_hist(const int* __restrict__ ei) {
    int e = blockIdx.x * blockDim.x + threadIdx.x;
    if (e < NE) atomicAdd(&g_deg[ei[NE + e]], 1);
}

__global__ void k_scan() {
    __shared__ int s[1024];
    const int CH = (NN + 1023) / 1024;
    int tid = threadIdx.x;
    int start = tid * CH;
    int sum = 0;
    for (int i = 0; i < CH; i++) {
        int idx = start + i;
        if (idx < NN) sum += g_deg[idx];
    }
    s[tid] = sum;
    __syncthreads();
    for (int off = 1; off < 1024; off <<= 1) {
        int v = 0;
        if (tid >= off) v = s[tid - off];
        __syncthreads();
        if (tid >= off) s[tid] += v;
        __syncthreads();
    }
    int run = (tid == 0) ? 0 : s[tid - 1];
    for (int i = 0; i < CH; i++) {
        int idx = start + i;
        if (idx < NN) {
            g_offs[idx] = run;
            g_cursor[idx] = run;
            run += g_deg[idx];
        }
    }
    if (tid == 1023) g_offs[NN] = s[1023];
}

__global__ void k_scatter(const int* __restrict__ ei) {
    int e = blockIdx.x * blockDim.x + threadIdx.x;
    if (e < NE) {
        int s = ei[e];
        int d = ei[NE + e];
        int pos = atomicAdd(&g_cursor[d], 1);
        g_ssrc[pos] = s;
        g_seid[pos] = e;
    }
}

// ---------------- weight prep: fp16 fragment order ----------------
__global__ void k_wprep(const float* __restrict__ W1, const float* __restrict__ W2) {
    int mat = blockIdx.x;           // 0..7 = layer*2 + (0:W1, 1:W2)
    int l = mat >> 1;
    const float* W = (mat & 1) ? (W2 + l * HID * HID) : (W1 + l * HID * HID);
    uint2* F = (uint2*)(g_wf + (size_t)mat * HID * HID);
    int n = threadIdx.x;            // 256
    int N8 = n >> 3, g = n & 7;
    for (int S = 0; S < 16; S++) {
        #pragma unroll
        for (int t = 0; t < 4; t++) {
            int k0 = S * 16 + 2 * t;
            float w0 = W[(k0    ) * HID + n];
            float w1 = W[(k0 + 1) * HID + n];
            float w8 = W[(k0 + 8) * HID + n];
            float w9 = W[(k0 + 9) * HID + n];
            F[(N8 * 16 + S) * 32 + g * 4 + t] = make_uint2(pack2(w0, w1), pack2(w8, w9));
        }
    }
}

// ---------------- node encoder ----------------
__global__ void k_enc(const float* __restrict__ x, const float* __restrict__ W,
                      const float* __restrict__ b) {
    __shared__ float sx[NDIM];
    int node = blockIdx.x;
    int c = threadIdx.x;
    if (c < NDIM) sx[c] = x[node * NDIM + c];
    __syncthreads();
    float a = b[c];
    #pragma unroll
    for (int k = 0; k < NDIM; k++) a += sx[k] * W[k * HID + c];
    float v = fmaxf(a, 0.f);
    g_h [(size_t)node * HID + c] = v;
    g_hh[(size_t)node * HID + c] = __float2half(v);
}

// ---------------- GINE aggregation -> fp16 fragment-order A ----------------
__global__ void k_aggregate(const float* __restrict__ edge_attr,
                            const float* __restrict__ eW,
                            const float* __restrict__ eb,
                            __half* __restrict__ Afrag) {
    __shared__ float sWt[EDIM * 256];   // [d][j*32 + l]
    for (int i = threadIdx.x; i < EDIM * 256; i += 256) {
        int d = i >> 8, c = i & 255;
        int S = c >> 4, k = c & 15;
        int t0 = (k >> 1) & 1, bb = k & 1, grp = k >> 2;
        int j = bb + ((grp & 1) << 2) + ((grp >> 1) << 1);
        int l = S * 2 + t0;
        sWt[d * 256 + j * 32 + l] = eW[i];
    }
    __syncthreads();
    int warp = threadIdx.x >> 5, l = threadIdx.x & 31;
    int node = blockIdx.x * 8 + warp;
    if (node >= NN) return;
    int S = l >> 1, t0 = l & 1;
    int base2 = S * 8 + t0;          // in 2-channel units

    float ebr[8];
    {
        const float2* eb2 = (const float2*)eb;
        float2 e0 = eb2[base2],     e1 = eb2[base2 + 4];
        float2 e2 = eb2[base2 + 2], e3 = eb2[base2 + 6];
        ebr[0]=e0.x; ebr[1]=e0.y; ebr[2]=e1.x; ebr[3]=e1.y;
        ebr[4]=e2.x; ebr[5]=e2.y; ebr[6]=e3.x; ebr[7]=e3.y;
    }
    float wj[8][EDIM];
    #pragma unroll
    for (int j = 0; j < 8; j++)
        #pragma unroll
        for (int d = 0; d < EDIM; d++) wj[j][d] = sWt[d * 256 + j * 32 + l];

    float acc[8] = {0,0,0,0,0,0,0,0};
    const unsigned* hh2 = (const unsigned*)g_hh;
    int e0i = g_offs[node], e1i = g_offs[node + 1];
    #pragma unroll 2
    for (int e = e0i; e < e1i; e++) {
        int src = g_ssrc[e];
        int eid = g_seid[e];
        float ea0 = edge_attr[eid*EDIM+0];
        float ea1 = edge_attr[eid*EDIM+1];
        float ea2 = edge_attr[eid*EDIM+2];
        float ea3 = edge_attr[eid*EDIM+3];
        float ea4 = edge_attr[eid*EDIM+4];
        size_t rb = (size_t)src * 128 + base2;
        float2 h0 = unpack2(hh2[rb]);
        float2 h1 = unpack2(hh2[rb + 4]);
        float2 h2 = unpack2(hh2[rb + 2]);
        float2 h3 = unpack2(hh2[rb + 6]);
        float hr[8] = {h0.x,h0.y,h1.x,h1.y,h2.x,h2.y,h3.x,h3.y};
        #pragma unroll
        for (int j = 0; j < 8; j++) {
            float m = hr[j] + ebr[j]
                    + ea0 * wj[j][0] + ea1 * wj[j][1] + ea2 * wj[j][2]
                    + ea3 * wj[j][3] + ea4 * wj[j][4];
            acc[j] += fmaxf(m, 0.f);
        }
    }
    const float2* h2p = (const float2*)g_h;
    size_t nb = (size_t)node * 128 + base2;
    float2 v0 = h2p[nb], v1 = h2p[nb + 4], v2 = h2p[nb + 2], v3 = h2p[nb + 6];
    float hv[8] = {v0.x,v0.y,v1.x,v1.y,v2.x,v2.y,v3.x,v3.y};
    float rv[8];
    #pragma unroll
    for (int j = 0; j < 8; j++) rv[j] = hv[j] + acc[j];

    int R = node >> 4, g = node & 7, h = (node >> 3) & 1;
    uint2* A2 = (uint2*)Afrag;
    size_t ubase = ((size_t)(R * 16 + S) * 2 + h) * 32;
    A2[ubase + g * 4 + t0]     = make_uint2(pack2(rv[0], rv[1]), pack2(rv[2], rv[3]));
    A2[ubase + g * 4 + t0 + 2] = make_uint2(pack2(rv[4], rv[5]), pack2(rv[6], rv[7]));
}

// ---------------- fused MLP: z2h = (relu(A@W1+b1))@W2 + b2, + BN stats -----
// 512 threads / 16 warps (2 row x 8 col), warp tile 64x32, block 128x256.
// K-chunk 32, double-buffered. z1 held in smem (fp16 fragment order).
// smem: A 2x8K @0, B 2x16K @16K, z1 64K @48K  => 112KB total.
#define MLP_SMEM 114688
__global__ void __launch_bounds__(512, 1)
k_mlp(const __half* __restrict__ Af, const __half* __restrict__ W1f,
      const __half* __restrict__ W2f, const float* __restrict__ b1,
      const float* __restrict__ b2, __half* __restrict__ Zh) {
    extern __shared__ char sm[];
    char* smA = sm;                       // 2 x 8KB
    char* smB = sm + 16384;               // 2 x 16KB
    uint2* smZ = (uint2*)(sm + 49152);    // 64KB

    const int tid = threadIdx.x;
    const int wid = tid >> 5, lane = tid & 31;
    const int g = lane >> 2, t = lane & 3;
    const int warpRow = wid >> 3;      // 0..1  (64 rows)
    const int wc = wid & 7;            // 0..7  (32 cols)
    const int bm = blockIdx.x * 128;
    const int Rbase = bm >> 4;
    const unsigned FULL = 0xffffffffu;

    float acc[4][4][4];

    auto load_A = [&](int buf, int st) {
        char* sA = smA + buf * 8192;
        int ch = tid;                     // 512 chunks of 16B
        int R = ch >> 6, rem = ch & 63;   // per R: 2 S-slices = 1KB contiguous
        const char* gp = (const char*)Af +
            (((size_t)(Rbase + R) * 16 + st * 2) * 512 + rem * 16);
        cp16(sA + ch * 16, gp);
    };
    auto load_B = [&](int buf, int st, const __half* Bf) {
        char* sB = smB + buf * 16384;
        #pragma unroll
        for (int i = 0; i < 2; i++) {
            int ch = tid + i * 512;       // 1024 chunks of 16B
            int N8 = ch >> 5, rem = ch & 31;  // per N8: 2 S-slices = 512B
            const char* gp = (const char*)Bf +
                (((size_t)N8 * 16 + st * 2) * 256 + rem * 16);
            cp16(sB + ch * 16, gp);
        }
    };

    // ================= phase 1: z1 = relu(A@W1 + b1) =================
    #pragma unroll
    for (int i = 0; i < 4; i++)
        #pragma unroll
        for (int j = 0; j < 4; j++) {
            acc[i][j][0]=0.f; acc[i][j][1]=0.f; acc[i][j][2]=0.f; acc[i][j][3]=0.f;
        }

    load_A(0, 0); load_B(0, 0, W1f);
    asm volatile("cp.async.commit_group;");
    for (int st = 0; st < 8; st++) {
        int buf = st & 1;
        if (st + 1 < 8) {
            load_A(buf ^ 1, st + 1); load_B(buf ^ 1, st + 1, W1f);
            asm volatile("cp.async.commit_group;");
            asm volatile("cp.async.wait_group 1;");
        } else {
            asm volatile("cp.async.wait_group 0;");
        }
        __syncthreads();
        const uint2* sA2 = (const uint2*)(smA + buf * 8192);
        const uint2* sB2 = (const uint2*)(smB + buf * 16384);
        #pragma unroll
        for (int Sl = 0; Sl < 2; Sl++) {
            unsigned af[4][4];
            unsigned bf[4][2];
            #pragma unroll
            for (int mt = 0; mt < 4; mt++) {
                int mtIdx = warpRow * 4 + mt;
                uint2 u0 = sA2[mtIdx * 128 + Sl * 64 + lane];
                uint2 u1 = sA2[mtIdx * 128 + Sl * 64 + 32 + lane];
                af[mt][0] = u0.x; af[mt][1] = u1.x; af[mt][2] = u0.y; af[mt][3] = u1.y;
            }
            #pragma unroll
            for (int nt = 0; nt < 4; nt++) {
                uint2 ub = sB2[(wc * 4 + nt) * 64 + Sl * 32 + lane];
                bf[nt][0] = ub.x; bf[nt][1] = ub.y;
            }
            #pragma unroll
            for (int mt = 0; mt < 4; mt++)
                #pragma unroll
                for (int nt = 0; nt < 4; nt++) {
                    asm volatile(
                        "mma.sync.aligned.m16n8k16.row.col.f32.f16.f16.f32 "
                        "{%0,%1,%2,%3}, {%4,%5,%6,%7}, {%8,%9}, {%0,%1,%2,%3};\n"
                        : "+f"(acc[mt][nt][0]), "+f"(acc[mt][nt][1]),
                          "+f"(acc[mt][nt][2]), "+f"(acc[mt][nt][3])
                        : "r"(af[mt][0]), "r"(af[mt][1]), "r"(af[mt][2]), "r"(af[mt][3]),
                          "r"(bf[nt][0]), "r"(bf[nt][1]));
                }
        }
        __syncthreads();
    }

    // prefetch W2 stage 0 (overlaps with z1 epilogue)
    load_B(0, 0, W2f);
    asm volatile("cp.async.commit_group;");

    // phase-1 epilogue: relu + b1 -> z1 smem fp16 frags (no shuffles)
    #pragma unroll
    for (int mt = 0; mt < 4; mt++) {
        int Rl = warpRow * 4 + mt;
        #pragma unroll
        for (int j = 0; j < 2; j++) {
            int S = wc * 2 + j;
            int ntA = 2 * j, ntB = 2 * j + 1;
            int cA = wc * 32 + ntA * 8 + 2 * t;
            int cB = cA + 8;
            float bA0 = b1[cA], bA1 = b1[cA + 1];
            float bB0 = b1[cB], bB1 = b1[cB + 1];
            float a0 = fmaxf(acc[mt][ntA][0] + bA0, 0.f);
            float a1 = fmaxf(acc[mt][ntA][1] + bA1, 0.f);
            float a2 = fmaxf(acc[mt][ntA][2] + bA0, 0.f);
            float a3 = fmaxf(acc[mt][ntA][3] + bA1, 0.f);
            float b0v = fmaxf(acc[mt][ntB][0] + bB0, 0.f);
            float b1v = fmaxf(acc[mt][ntB][1] + bB1, 0.f);
            float b2v = fmaxf(acc[mt][ntB][2] + bB0, 0.f);
            float b3v = fmaxf(acc[mt][ntB][3] + bB1, 0.f);
            int ubase = ((Rl * 16 + S) * 2) * 32;
            smZ[ubase + lane]      = make_uint2(pack2(a0, a1), pack2(b0v, b1v));
            smZ[ubase + 32 + lane] = make_uint2(pack2(a2, a3), pack2(b2v, b3v));
        }
    }

    // ================= phase 2: z2 = z1 @ W2 + b2 =================
    #pragma unroll
    for (int i = 0; i < 4; i++)
        #pragma unroll
        for (int j = 0; j < 4; j++) {
            acc[i][j][0]=0.f; acc[i][j][1]=0.f; acc[i][j][2]=0.f; acc[i][j][3]=0.f;
        }
    __syncthreads();   // z1 visible to all warps

    for (int st = 0; st < 8; st++) {
        int buf = st & 1;
        if (st + 1 < 8) {
            load_B(buf ^ 1, st + 1, W2f);
            asm volatile("cp.async.commit_group;");
            asm volatile("cp.async.wait_group 1;");
        } else {
            asm volatile("cp.async.wait_group 0;");
        }
        __syncthreads();
        const uint2* sB2 = (const uint2*)(smB + buf * 16384);
        #pragma unroll
        for (int Sl = 0; Sl < 2; Sl++) {
            int S = st * 2 + Sl;
            unsigned af[4][4];
            unsigned bf[4][2];
            #pragma unroll
            for (int mt = 0; mt < 4; mt++) {
                int mtIdx = warpRow * 4 + mt;
                uint2 u0 = smZ[((mtIdx * 16 + S) * 2 + 0) * 32 + lane];
                uint2 u1 = smZ[((mtIdx * 16 + S) * 2 + 1) * 32 + lane];
                af[mt][0] = u0.x; af[mt][1] = u1.x; af[mt][2] = u0.y; af[mt][3] = u1.y;
            }
            #pragma unroll
            for (int nt = 0; nt < 4; nt++) {
                uint2 ub = sB2[(wc * 4 + nt) * 64 + Sl * 32 + lane];
                bf[nt][0] = ub.x; bf[nt][1] = ub.y;
            }
            #pragma unroll
            for (int mt = 0; mt < 4; mt++)
                #pragma unroll
                for (int nt = 0; nt < 4; nt++) {
                    asm volatile(
                        "mma.sync.aligned.m16n8k16.row.col.f32.f16.f16.f32 "
                        "{%0,%1,%2,%3}, {%4,%5,%6,%7}, {%8,%9}, {%0,%1,%2,%3};\n"
                        : "+f"(acc[mt][nt][0]), "+f"(acc[mt][nt][1]),
                          "+f"(acc[mt][nt][2]), "+f"(acc[mt][nt][3])
                        : "r"(af[mt][0]), "r"(af[mt][1]), "r"(af[mt][2]), "r"(af[mt][3]),
                          "r"(bf[nt][0]), "r"(bf[nt][1]));
                }
        }
        __syncthreads();
    }

    // phase-2 epilogue: fp16 z2 + fused BN sums (stats from exact fp32)
    unsigned* Z1 = (unsigned*)Zh;
    #pragma unroll
    for (int nt = 0; nt < 4; nt++) {
        int c0 = wc * 32 + nt * 8 + 2 * t;
        float b0 = b2[c0], b1v = b2[c0 + 1];
        float s0 = 0.f, q0 = 0.f, s1 = 0.f, q1 = 0.f;
        #pragma unroll
        for (int mt = 0; mt < 4; mt++) {
            int r0 = bm + warpRow * 64 + mt * 16 + g;
            int r1 = r0 + 8;
            float v0 = acc[mt][nt][0] + b0;
            float v1 = acc[mt][nt][1] + b1v;
            float v2 = acc[mt][nt][2] + b0;
            float v3 = acc[mt][nt][3] + b1v;
            if (r0 < NN) {
                Z1[((size_t)r0 * HID + c0) >> 1] = pack2(v0, v1);
                s0 += v0; q0 += v0 * v0; s1 += v1; q1 += v1 * v1;
            }
            if (r1 < NN) {
                Z1[((size_t)r1 * HID + c0) >> 1] = pack2(v2, v3);
                s0 += v2; q0 += v2 * v2; s1 += v3; q1 += v3 * v3;
            }
        }
        #pragma unroll
        for (int off = 16; off >= 4; off >>= 1) {
            s0 += __shfl_down_sync(FULL, s0, off);
            q0 += __shfl_down_sync(FULL, q0, off);
            s1 += __shfl_down_sync(FULL, s1, off);
            q1 += __shfl_down_sync(FULL, q1, off);
        }
        if (lane < 4) {
            atomicAdd(&g_bnsum[c0],           s0);
            atomicAdd(&g_bnsum[c0 + 1],       s1);
            atomicAdd(&g_bnsum[HID + c0],     q0);
            atomicAdd(&g_bnsum[HID + c0 + 1], q1);
        }
    }
}

// ---------------- fp32 SIMT GEMM (head only) ----------------
template <int RELU>
__global__ void k_gemm(const float* __restrict__ A, const float* __restrict__ B,
                       const float* __restrict__ bias, float* __restrict__ C,
                       int M, int N, int K) {
    __shared__ float As[16][64];
    __shared__ float Bs[16][64];
    int tid = threadIdx.x;
    int tx = tid & 15, ty = tid >> 4;
    int bm = blockIdx.x * 64, bn = blockIdx.y * 64;
    int aR = tid >> 2;
    int aC = (tid & 3) * 4;
    int bR = tid >> 4;
    int bC = (tid & 15) * 4;
    int gArow = bm + aR;
    float acc[4][4] = {};
    for (int k0 = 0; k0 < K; k0 += 16) {
        float4 av = (gArow < M) ? *(const float4*)(A + (size_t)gArow * K + k0 + aC)
                                : make_float4(0.f, 0.f, 0.f, 0.f);
        As[aC + 0][aR] = av.x;
        As[aC + 1][aR] = av.y;
        As[aC + 2][aR] = av.z;
        As[aC + 3][aR] = av.w;
        *(float4*)&Bs[bR][bC] = *(const float4*)(B + (size_t)(k0 + bR) * N + bn + bC);
        __syncthreads();
        #pragma unroll
        for (int k = 0; k < 16; k++) {
            float4 a4 = *(const float4*)&As[k][ty * 4];
            float4 b4 = *(const float4*)&Bs[k][tx * 4];
            float ar[4] = {a4.x, a4.y, a4.z, a4.w};
            float br[4] = {b4.x, b4.y, b4.z, b4.w};
            #pragma unroll
            for (int i = 0; i < 4; i++)
                #pragma unroll
                for (int j = 0; j < 4; j++)
                    acc[i][j] += ar[i] * br[j];
        }
        __syncthreads();
    }
    #pragma unroll
    for (int i = 0; i < 4; i++) {
        int r = bm + ty * 4 + i;
        if (r < M) {
            #pragma unroll
            for (int j = 0; j < 4; j++) {
                int c = bn + tx * 4 + j;
                float v = acc[i][j] + bias[c];
                if (RELU) v = fmaxf(v, 0.f);
                C[(size_t)r * N + c] = v;
            }
        }
    }
}

// ---------------- batchnorm ----------------
__global__ void k_bn_fin(const float* __restrict__ gamma, const float* __restrict__ beta) {
    int c = threadIdx.x;
    float mu = g_bnsum[c] * (1.f / NN);
    float var = g_bnsum[HID + c] * (1.f / NN) - mu * mu;
    float inv = rsqrtf(var + BN_EPS);
    float sc = inv * gamma[c];
    g_bnscale[c] = sc;
    g_bnshift[c] = beta[c] - mu * sc;
    g_bnsum[c] = 0.f;
    g_bnsum[HID + c] = 0.f;
}

__global__ void k_bn_apply() {
    int idx = blockIdx.x * blockDim.x + threadIdx.x;   // 4-channel unit
    if (idx < NN * 64) {
        int c4 = idx & 63;
        uint2 zu = ((const uint2*)g_z2h)[idx];
        float2 z01 = unpack2(zu.x);
        float2 z23 = unpack2(zu.y);
        float4 sc = ((const float4*)g_bnscale)[c4];
        float4 sh = ((const float4*)g_bnshift)[c4];
        float4 hv = ((const float4*)g_h)[idx];
        float4 r;
        r.x = fmaxf(z01.x * sc.x + sh.x, 0.f) + hv.x;
        r.y = fmaxf(z01.y * sc.y + sh.y, 0.f) + hv.y;
        r.z = fmaxf(z23.x * sc.z + sh.z, 0.f) + hv.z;
        r.w = fmaxf(z23.y * sc.w + sh.w, 0.f) + hv.w;
        ((float4*)g_h)[idx] = r;
        ((uint2*)g_hh)[idx] = make_uint2(pack2(r.x, r.y), pack2(r.z, r.w));
    }
}

// ---------------- pooling ----------------
__global__ void k_pool(const int* __restrict__ batch) {
    __shared__ int sb[128];
    int c = threadIdx.x;
    int n0 = blockIdx.x * 128;
    int n1 = min(n0 + 128, NN);
    if (c < 128 && n0 + c < NN) sb[c] = batch[n0 + c];
    __syncthreads();
    float accS = 0.f, accM = 0.f;
    int cur = sb[0];
    int cnt = 0;
    for (int n = n0; n < n1; n++) {
        int gg = sb[n - n0];
        if (gg != cur) {
            atomicAdd(&g_psum[cur * HID + c], accS);
            atomicMax((int*)&g_pmax[cur * HID + c], __float_as_int(accM));
            if (c == 0) atomicAdd(&g_cnt[cur], cnt);
            accS = 0.f; accM = 0.f; cnt = 0; cur = gg;
        }
        float v = g_h[(size_t)n * HID + c];
        accS += v;
        accM = fmaxf(accM, v);
        cnt++;
    }
    atomicAdd(&g_psum[cur * HID + c], accS);
    atomicMax((int*)&g_pmax[cur * HID + c], __float_as_int(accM));
    if (c == 0) atomicAdd(&g_cnt[cur], cnt);
}

__global__ void k_pool_fin() {
    int g = blockIdx.x, c = threadIdx.x;
    float s = g_psum[g * HID + c];
    float cnt = (float)max(g_cnt[g], 1);
    g_gfeat[g * 3 * HID + c]            = s / cnt;
    g_gfeat[g * 3 * HID + HID + c]      = s;
    g_gfeat[g * 3 * HID + 2 * HID + c]  = g_pmax[g * HID + c];
}

// ---------------- head final ----------------
__global__ void k_final(const float* __restrict__ W3, const float* __restrict__ b3,
                        float* __restrict__ out) {
    __shared__ float red[128];
    int g = blockIdx.x, t = threadIdx.x;
    red[t] = g_h2[g * 128 + t] * W3[t];
    __syncthreads();
    for (int off = 64; off > 0; off >>= 1) {
        if (t < off) red[t] += red[t + off];
        __syncthreads();
    }
    if (t == 0) out[g] = red[0] + b3[0];
}

// ---------------- launch ----------------
extern "C" void kernel_launch(void* const* d_in, const int* in_sizes, int n_in,
                              void* d_out, int out_size) {
    const float* x     = (const float*)d_in[0];
    const int*   ei    = (const int*)  d_in[1];
    const float* eattr = (const float*)d_in[2];
    const int*   batch = (const int*)  d_in[3];
    const float* encW  = (const float*)d_in[4];
    const float* encb  = (const float*)d_in[5];
    const float* edgeW = (const float*)d_in[6];
    const float* edgeb = (const float*)d_in[7];
    const float* W1    = (const float*)d_in[8];
    const float* b1    = (const float*)d_in[9];
    const float* W2    = (const float*)d_in[10];
    const float* b2    = (const float*)d_in[11];
    const float* bng   = (const float*)d_in[12];
    const float* bnb   = (const float*)d_in[13];
    const float* hW1   = (const float*)d_in[14];
    const float* hb1   = (const float*)d_in[15];
    const float* hW2   = (const float*)d_in[16];
    const float* hb2   = (const float*)d_in[17];
    const float* hW3   = (const float*)d_in[18];
    const float* hb3   = (const float*)d_in[19];
    float* out = (float*)d_out;

    float *p_gf, *p_h1, *p_h2;
    __half *p_a0f, *p_wf, *p_z2h;
    cudaGetSymbolAddress((void**)&p_gf, g_gfeat);
    cudaGetSymbolAddress((void**)&p_h1, g_h1);
    cudaGetSymbolAddress((void**)&p_h2, g_h2);
    cudaGetSymbolAddress((void**)&p_a0f, g_a0f);
    cudaGetSymbolAddress((void**)&p_wf, g_wf);
    cudaGetSymbolAddress((void**)&p_z2h, g_z2h);

    cudaFuncSetAttribute(k_mlp, cudaFuncAttributeMaxDynamicSharedMemorySize, MLP_SMEM);

    // CSR build + init + weight prep
    k_zero_init<<<512, 256>>>();
    k_hist<<<(NE + 255) / 256, 256>>>(ei);
    k_scan<<<1, 1024>>>();
    k_scatter<<<(NE + 255) / 256, 256>>>(ei);
    k_wprep<<<8, 256>>>(W1, W2);

    // encoder
    k_enc<<<NN, HID>>>(x, encW, encb);

    for (int l = 0; l < NL; l++) {
        k_aggregate<<<(NN + 7) / 8, 256>>>(eattr, edgeW + l * EDIM * HID, edgeb + l * HID, p_a0f);
        k_mlp<<<NNPAD / 128, 512, MLP_SMEM>>>(
            p_a0f,
            p_wf + (size_t)(l * 2 + 0) * HID * HID,
            p_wf + (size_t)(l * 2 + 1) * HID * HID,
            b1 + l * HID, b2 + l * HID, p_z2h);
        k_bn_fin<<<1, 256>>>(bng + l * HID, bnb + l * HID);
        k_bn_apply<<<(NN * 64 + 511) / 512, 512>>>();
    }

    // pooling + head
    k_pool<<<(NN + 127) / 128, 256>>>(batch);
    k_pool_fin<<<NG, HID>>>();
    k_gemm<1><<<dim3(NG / 64, HID / 64), 256>>>(p_gf, hW1, hb1, p_h1, NG, HID, 3 * HID);
    k_gemm<1><<<dim3(NG / 64, (HID / 2) / 64), 256>>>(p_h1, hW2, hb2, p_h2, NG, HID / 2, HID);
    k_final<<<NG, 128>>>(hW3, hb3, out);
}